// round 2
// baseline (speedup 1.0000x reference)
#include <cuda_runtime.h>
#include <math.h>

#define LYR 6
#define BB  16
#define HH  384
#define TT  2048
#define N2  32
#define HF  1536

// ---------------- scratch (device globals; no allocation allowed) ----------------
__device__ float g_y [BB*HH*TT];   // scan/gelu output, later reused as FFN2 output
__device__ float g_s4[BB*HH*TT];   // GLU output
__device__ float g_x1[BB*HH*TT];   // LN1 output
__device__ float g_xb[BB*HH*TT];   // ping-pong x between layers
__device__ float g_h1[BB*HF*TT];   // Wout z-buffer (768 rows) / FFN hidden (1536 rows)

// ---------------- S4D recurrence scan: y = gelu(conv(x*mask,K) + D*x*mask) -------
__global__ void scan_kernel(const float* __restrict__ x, const float* __restrict__ mask,
                            const float* __restrict__ log_dt,
                            const float* __restrict__ A_re, const float* __restrict__ A_im,
                            const float* __restrict__ C_re, const float* __restrict__ C_im,
                            const float* __restrict__ Dp,
                            float* __restrict__ y, int layer)
{
    int wid  = (blockIdx.x * blockDim.x + threadIdx.x) >> 5;
    int lane = threadIdx.x & 31;
    if (wid >= BB * HH) return;
    int b = wid / HH, h = wid % HH;

    float dt = expf(log_dt[layer*HH + h]);
    int pidx = (layer*HH + h) * N2 + lane;
    float ar = A_re[pidx], ai = A_im[pidx];
    float dre = ar * dt, dim = ai * dt;
    float e   = expf(dre);
    float wre = e * cosf(dim);
    float wim = e * sinf(dim);
    // (exp(dtA)-1)/A
    float nre = wre - 1.0f, nim = wim;
    float d2  = ar*ar + ai*ai;
    float qre = (nre*ar + nim*ai) / d2;
    float qim = (nim*ar - nre*ai) / d2;
    float cre = C_re[pidx], cim = C_im[pidx];
    float cdre = cre*qre - cim*qim;
    float cdim = cre*qim + cim*qre;
    float Dv = Dp[layer*HH + h];

    const float* xr = x + (size_t)(b*HH + h) * TT;
    const float* mr = mask + (size_t)b * TT;
    float* yr = y + (size_t)(b*HH + h) * TT;

    float sre = 0.f, sim = 0.f;
    #pragma unroll 4
    for (int t = 0; t < TT; ++t) {
        float xv = xr[t] * mr[t];
        float tre = fmaf(wre, sre, fmaf(-wim, sim, xv));
        float tim = fmaf(wre, sim, wim * sre);
        sre = tre; sim = tim;
        float contrib = fmaf(cdre, sre, -cdim * sim);
        #pragma unroll
        for (int off = 16; off; off >>= 1)
            contrib += __shfl_xor_sync(0xffffffffu, contrib, off);
        if (lane == 0) {
            float yv = 2.0f * contrib + Dv * xv;
            yr[t] = 0.5f * yv * (1.0f + erff(yv * 0.70710678118654752f));
        }
    }
}

// ---------------- generic fp32 GEMM: Out[b,m,t] = sum_k W[m,k]*X[b,k,t] + bias --
// grid (TT/128, M/128, B), block 256
template<bool MIN, bool RELU_, bool MOUT>
__global__ __launch_bounds__(256)
void gemm_kernel(const float* __restrict__ W, const float* __restrict__ X,
                 const float* __restrict__ bias, const float* __restrict__ mask,
                 float* __restrict__ Out, int M, int K)
{
    __shared__ float As[8][128];
    __shared__ float Bs[8][128];

    int b  = blockIdx.z;
    int m0 = blockIdx.y * 128;
    int t0 = blockIdx.x * 128;
    int tid = threadIdx.x;
    int tx = tid & 15, ty = tid >> 4;

    float acc[8][8];
    #pragma unroll
    for (int i = 0; i < 8; ++i)
        #pragma unroll
        for (int j = 0; j < 8; ++j) acc[i][j] = 0.f;

    int a_m = tid >> 1;          // 0..127
    int a_k = (tid & 1) * 4;     // 0 or 4
    int b_k = tid >> 5;          // 0..7
    int b_t = (tid & 31) * 4;    // 0..124

    const float* Wp = W + (size_t)(m0 + a_m) * K + a_k;
    const float* Xp = X + ((size_t)b * K + b_k) * TT + t0 + b_t;

    float4 mvec = make_float4(1.f, 1.f, 1.f, 1.f);
    if (MIN) mvec = *(const float4*)(mask + (size_t)b*TT + t0 + b_t);

    for (int k0 = 0; k0 < K; k0 += 8) {
        float4 av = *(const float4*)(Wp + k0);
        float4 bv = *(const float4*)(Xp + (size_t)k0 * TT);
        if (MIN) { bv.x *= mvec.x; bv.y *= mvec.y; bv.z *= mvec.z; bv.w *= mvec.w; }
        As[a_k + 0][a_m] = av.x;
        As[a_k + 1][a_m] = av.y;
        As[a_k + 2][a_m] = av.z;
        As[a_k + 3][a_m] = av.w;
        *(float4*)&Bs[b_k][b_t] = bv;
        __syncthreads();
        #pragma unroll
        for (int kk = 0; kk < 8; ++kk) {
            float4 a0 = *(float4*)&As[kk][ty*4];
            float4 a1 = *(float4*)&As[kk][ty*4 + 64];
            float4 b0 = *(float4*)&Bs[kk][tx*4];
            float4 b1 = *(float4*)&Bs[kk][tx*4 + 64];
            float am[8] = {a0.x,a0.y,a0.z,a0.w,a1.x,a1.y,a1.z,a1.w};
            float bn[8] = {b0.x,b0.y,b0.z,b0.w,b1.x,b1.y,b1.z,b1.w};
            #pragma unroll
            for (int i = 0; i < 8; ++i)
                #pragma unroll
                for (int j = 0; j < 8; ++j)
                    acc[i][j] = fmaf(am[i], bn[j], acc[i][j]);
        }
        __syncthreads();
    }

    #pragma unroll
    for (int i = 0; i < 8; ++i) {
        int mm = m0 + ((i < 4) ? (ty*4 + i) : (64 + ty*4 + (i - 4)));
        float bi = bias[mm];
        float* orow = Out + ((size_t)b * M + mm) * TT + t0;
        #pragma unroll
        for (int jh = 0; jh < 2; ++jh) {
            int tc = tx*4 + jh*64;
            float4 v;
            v.x = acc[i][jh*4+0] + bi;
            v.y = acc[i][jh*4+1] + bi;
            v.z = acc[i][jh*4+2] + bi;
            v.w = acc[i][jh*4+3] + bi;
            if (RELU_) {
                v.x = fmaxf(v.x, 0.f); v.y = fmaxf(v.y, 0.f);
                v.z = fmaxf(v.z, 0.f); v.w = fmaxf(v.w, 0.f);
            }
            if (MOUT) {
                float4 mo = *(const float4*)(mask + (size_t)b*TT + t0 + tc);
                v.x *= mo.x; v.y *= mo.y; v.z *= mo.z; v.w *= mo.w;
            }
            *(float4*)(orow + tc) = v;
        }
    }
}

// ---------------- GLU: s4[b,o,t] = z[b,o,t] * sigmoid(z[b,o+H,t]) ----------------
__global__ void glu_kernel(const float* __restrict__ z, float* __restrict__ out)
{
    int idx = blockIdx.x * blockDim.x + threadIdx.x;
    if (idx >= BB*HH*TT) return;
    int t = idx % TT;
    int rem = idx / TT;
    int o = rem % HH;
    int b = rem / HH;
    float a = z[((size_t)b * (2*HH) + o) * TT + t];
    float g = z[((size_t)b * (2*HH) + o + HH) * TT + t];
    out[idx] = a / (1.0f + expf(-g));
}

// ---------------- channel LayerNorm with residual --------------------------------
// grid (TT/64, B), block 256, dyn smem HH*64*4 bytes
template<bool MASK_RES, bool MASK_OUT>
__global__ __launch_bounds__(256)
void ln_kernel(const float* __restrict__ in1, const float* __restrict__ in2,
               const float* __restrict__ mask,
               const float* __restrict__ gamma, const float* __restrict__ beta,
               float* __restrict__ out)
{
    extern __shared__ float v[];            // [HH][64]
    __shared__ float rsum[4][64], rsq[4][64], mean_s[64], rstd_s[64];

    int b = blockIdx.y, t0 = blockIdx.x * 64, tid = threadIdx.x;
    const float* m = mask + (size_t)b * TT + t0;

    #pragma unroll 4
    for (int it = 0; it < (HH*64)/256; ++it) {   // 96 iters
        int idx = it * 256 + tid;
        int h = idx >> 6, t = idx & 63;
        size_t g = ((size_t)(b*HH + h)) * TT + t0 + t;
        float a = in1[g];
        if (MASK_RES) a *= m[t];
        v[idx] = a + in2[g];
    }
    __syncthreads();

    int grp = tid >> 6, lt = tid & 63;
    float s = 0.f, q = 0.f;
    for (int h = grp*96; h < grp*96 + 96; ++h) {
        float w = v[h*64 + lt];
        s += w; q += w*w;
    }
    rsum[grp][lt] = s; rsq[grp][lt] = q;
    __syncthreads();
    if (grp == 0) {
        float ts = rsum[0][lt] + rsum[1][lt] + rsum[2][lt] + rsum[3][lt];
        float tq = rsq [0][lt] + rsq [1][lt] + rsq [2][lt] + rsq [3][lt];
        float mu = ts * (1.0f / HH);
        float var = tq * (1.0f / HH) - mu * mu;
        mean_s[lt] = mu;
        rstd_s[lt] = rsqrtf(var + 1e-4f);
    }
    __syncthreads();

    #pragma unroll 4
    for (int it = 0; it < (HH*64)/256; ++it) {
        int idx = it * 256 + tid;
        int h = idx >> 6, t = idx & 63;
        float w = (v[idx] - mean_s[t]) * rstd_s[t] * gamma[h] + beta[h];
        if (MASK_OUT) w *= m[t];
        out[((size_t)(b*HH + h)) * TT + t0 + t] = w;
    }
}

// ---------------- host launch -----------------------------------------------------
extern "C" void kernel_launch(void* const* d_in, const int* in_sizes, int n_in,
                              void* d_out, int out_size)
{
    (void)in_sizes; (void)n_in; (void)out_size;
    const float* x      = (const float*)d_in[0];
    const float* mask   = (const float*)d_in[1];
    const float* log_dt = (const float*)d_in[2];
    const float* A_re   = (const float*)d_in[3];
    const float* A_im   = (const float*)d_in[4];
    const float* C_re   = (const float*)d_in[5];
    const float* C_im   = (const float*)d_in[6];
    const float* Dp     = (const float*)d_in[7];
    const float* Wout   = (const float*)d_in[8];
    const float* bout   = (const float*)d_in[9];
    const float* g1     = (const float*)d_in[10];
    const float* be1    = (const float*)d_in[11];
    const float* W1     = (const float*)d_in[12];
    const float* bf1    = (const float*)d_in[13];
    const float* W2     = (const float*)d_in[14];
    const float* bf2    = (const float*)d_in[15];
    const float* g2     = (const float*)d_in[16];
    const float* be2    = (const float*)d_in[17];

    float *gy, *gs4, *gx1, *gxb, *gh1;
    cudaGetSymbolAddress((void**)&gy,  g_y);
    cudaGetSymbolAddress((void**)&gs4, g_s4);
    cudaGetSymbolAddress((void**)&gx1, g_x1);
    cudaGetSymbolAddress((void**)&gxb, g_xb);
    cudaGetSymbolAddress((void**)&gh1, g_h1);

    const int LN_SMEM = HH * 64 * 4;
    cudaFuncSetAttribute(ln_kernel<true,  false>, cudaFuncAttributeMaxDynamicSharedMemorySize, LN_SMEM);
    cudaFuncSetAttribute(ln_kernel<false, false>, cudaFuncAttributeMaxDynamicSharedMemorySize, LN_SMEM);
    cudaFuncSetAttribute(ln_kernel<false, true >, cudaFuncAttributeMaxDynamicSharedMemorySize, LN_SMEM);

    const float* xcur = x;
    for (int l = 0; l < LYR; ++l) {
        // 1. S4D scan + D-skip + GELU -> g_y
        scan_kernel<<<(BB*HH)/4, 128>>>(xcur, mask, log_dt, A_re, A_im, C_re, C_im, Dp, gy, l);

        // 2. z = Wout @ y + bout   (M=768) -> g_h1 (as z-buffer)
        gemm_kernel<false, false, false><<<dim3(TT/128, (2*HH)/128, BB), 256>>>(
            Wout + (size_t)l*2*HH*HH, gy, bout + (size_t)l*2*HH, mask, gh1, 2*HH, HH);

        // 3. GLU -> g_s4
        glu_kernel<<<(BB*HH*TT + 255)/256, 256>>>(gh1, gs4);

        // 4. LN1( x*mask + s4 ) -> g_x1
        ln_kernel<true, false><<<dim3(TT/64, BB), 256, LN_SMEM>>>(
            xcur, gs4, mask, g1 + (size_t)l*HH, be1 + (size_t)l*HH, gx1);

        // 5. h = relu(W1 @ (x1*mask) + bf1) -> g_h1
        gemm_kernel<true, true, false><<<dim3(TT/128, HF/128, BB), 256>>>(
            W1 + (size_t)l*HF*HH, gx1, bf1 + (size_t)l*HF, mask, gh1, HF, HH);

        // 6. o = (W2 @ (h*mask) + bf2) * mask -> g_y (reuse)
        gemm_kernel<true, false, true><<<dim3(TT/128, HH/128, BB), 256>>>(
            W2 + (size_t)l*HH*HF, gh1, bf2 + (size_t)l*HH, mask, gy, HH, HF);

        // 7. LN2( x1 + o ) -> next x (final layer: *mask into d_out)
        if (l == LYR - 1) {
            ln_kernel<false, true><<<dim3(TT/64, BB), 256, LN_SMEM>>>(
                gx1, gy, mask, g2 + (size_t)l*HH, be2 + (size_t)l*HH, (float*)d_out);
        } else {
            ln_kernel<false, false><<<dim3(TT/64, BB), 256, LN_SMEM>>>(
                gx1, gy, mask, g2 + (size_t)l*HH, be2 + (size_t)l*HH, gxb);
        }
        xcur = gxb;
    }
}

// round 4
// speedup vs baseline: 1.3895x; 1.3895x over previous
#include <cuda_runtime.h>
#include <cuda_bf16.h>
#include <math.h>
#include <stdint.h>

#define LYR 6
#define BB  16
#define HH  384
#define TT  2048
#define N2  32
#define HF  1536

// ---------------- scratch (device globals; no allocation allowed) ----------------
__device__ float g_y [BB*HH*TT];   // scan/gelu output, later reused as FFN2 output
__device__ float g_s4[BB*HH*TT];   // GLU output
__device__ float g_x1[BB*HH*TT];   // LN1 output
__device__ float g_xb[BB*HH*TT];   // ping-pong x between layers
__device__ float g_h1[BB*HF*TT];   // Wout z-buffer (768 rows) / FFN hidden (1536 rows)

__device__ __nv_bfloat16 g_whi[HF*HH];            // converted weight (hi)
__device__ __nv_bfloat16 g_wlo[HF*HH];            // converted weight (lo)
__device__ __nv_bfloat16 g_xhi[(size_t)BB*TT*HF]; // transposed activation (hi) [B,T,K]
__device__ __nv_bfloat16 g_xlo[(size_t)BB*TT*HF]; // transposed activation (lo)

// ================= helpers (base ISA only: cp.async / ldmatrix / mma.sync) =======
__device__ __forceinline__ uint32_t smem_u32(const void* p) {
    uint32_t a;
    asm("{ .reg .u64 t; cvta.to.shared.u64 t, %1; cvt.u32.u64 %0, t; }" : "=r"(a) : "l"(p));
    return a;
}
__device__ __forceinline__ void cpasync16(uint32_t saddr, const void* g) {
    asm volatile("cp.async.cg.shared.global [%0], [%1], 16;" :: "r"(saddr), "l"(g));
}
#define CP_COMMIT() asm volatile("cp.async.commit_group;" ::: "memory")
#define CP_WAIT(n)  asm volatile("cp.async.wait_group %0;" :: "n"(n) : "memory")

__device__ __forceinline__ void ldmat4(uint32_t* r, uint32_t a) {
    asm volatile("ldmatrix.sync.aligned.m8n8.x4.shared.b16 {%0,%1,%2,%3}, [%4];"
        : "=r"(r[0]), "=r"(r[1]), "=r"(r[2]), "=r"(r[3]) : "r"(a));
}
__device__ __forceinline__ void ldmat2(uint32_t* r, uint32_t a) {
    asm volatile("ldmatrix.sync.aligned.m8n8.x2.shared.b16 {%0,%1}, [%2];"
        : "=r"(r[0]), "=r"(r[1]) : "r"(a));
}
__device__ __forceinline__ void mma_bf16(float* d, const uint32_t* a, const uint32_t* b) {
    asm volatile("mma.sync.aligned.m16n8k16.row.col.f32.bf16.bf16.f32 "
        "{%0,%1,%2,%3}, {%4,%5,%6,%7}, {%8,%9}, {%0,%1,%2,%3};"
        : "+f"(d[0]), "+f"(d[1]), "+f"(d[2]), "+f"(d[3])
        : "r"(a[0]), "r"(a[1]), "r"(a[2]), "r"(a[3]), "r"(b[0]), "r"(b[1]));
}

// ---------------- S4D recurrence scan: y = gelu(conv(x*mask,K) + D*x*mask) -------
__global__ void scan_kernel(const float* __restrict__ x, const float* __restrict__ mask,
                            const float* __restrict__ log_dt,
                            const float* __restrict__ A_re, const float* __restrict__ A_im,
                            const float* __restrict__ C_re, const float* __restrict__ C_im,
                            const float* __restrict__ Dp,
                            float* __restrict__ y, int layer)
{
    int wid  = (blockIdx.x * blockDim.x + threadIdx.x) >> 5;
    int lane = threadIdx.x & 31;
    if (wid >= BB * HH) return;
    int b = wid / HH, h = wid % HH;

    float dt = expf(log_dt[layer*HH + h]);
    int pidx = (layer*HH + h) * N2 + lane;
    float ar = A_re[pidx], ai = A_im[pidx];
    float dre = ar * dt, dim = ai * dt;
    float e   = expf(dre);
    float wre = e * cosf(dim);
    float wim = e * sinf(dim);
    float nre = wre - 1.0f, nim = wim;
    float d2  = ar*ar + ai*ai;
    float qre = (nre*ar + nim*ai) / d2;
    float qim = (nim*ar - nre*ai) / d2;
    float cre = C_re[pidx], cim = C_im[pidx];
    float cdre = cre*qre - cim*qim;
    float cdim = cre*qim + cim*qre;
    float Dv = Dp[layer*HH + h];

    const float* xr = x + (size_t)(b*HH + h) * TT;
    const float* mr = mask + (size_t)b * TT;
    float* yr = y + (size_t)(b*HH + h) * TT;

    float sre = 0.f, sim = 0.f;
    #pragma unroll 4
    for (int t = 0; t < TT; ++t) {
        float xv = xr[t] * mr[t];
        float tre = fmaf(wre, sre, fmaf(-wim, sim, xv));
        float tim = fmaf(wre, sim, wim * sre);
        sre = tre; sim = tim;
        float contrib = fmaf(cdre, sre, -cdim * sim);
        #pragma unroll
        for (int off = 16; off; off >>= 1)
            contrib += __shfl_xor_sync(0xffffffffu, contrib, off);
        if (lane == 0) {
            float yv = 2.0f * contrib + Dv * xv;
            yr[t] = 0.5f * yv * (1.0f + erff(yv * 0.70710678118654752f));
        }
    }
}

// ---------------- conversions ------------------------------------------------------
__global__ void convw_kernel(const float* __restrict__ W,
                             __nv_bfloat16* __restrict__ hi, __nv_bfloat16* __restrict__ lo,
                             int n)
{
    int i = blockIdx.x * blockDim.x + threadIdx.x;
    if (i >= n) return;
    float w = W[i];
    __nv_bfloat16 h = __float2bfloat16(w);
    hi[i] = h;
    lo[i] = __float2bfloat16(w - __bfloat162float(h));
}

// X: [B, K, T] (t contig) -> out hi/lo: [B, T, K] (k contig), optionally *mask
template<bool MASKIN>
__global__ void convx_kernel(const float* __restrict__ X, const float* __restrict__ mask,
                             __nv_bfloat16* __restrict__ hi, __nv_bfloat16* __restrict__ lo,
                             int K)
{
    __shared__ float tile[32][33];
    int b = blockIdx.z;
    int t0 = blockIdx.x * 32, k0 = blockIdx.y * 32;
    int tx = threadIdx.x, ty = threadIdx.y;   // block (32, 8)
    float mv = 1.f;
    if (MASKIN) mv = mask[(size_t)b*TT + t0 + tx];
    #pragma unroll
    for (int i = 0; i < 4; ++i) {
        int k = k0 + ty + i*8;
        tile[ty + i*8][tx] = X[((size_t)b*K + k)*TT + t0 + tx] * mv;
    }
    __syncthreads();
    #pragma unroll
    for (int i = 0; i < 4; ++i) {
        int t = t0 + ty + i*8;
        float v = tile[tx][ty + i*8];
        __nv_bfloat16 h = __float2bfloat16(v);
        size_t o = ((size_t)b*TT + t)*K + k0 + tx;
        hi[o] = h;
        lo[o] = __float2bfloat16(v - __bfloat162float(h));
    }
}

// ---------------- split-bf16 mma.sync GEMM -----------------------------------------
// Out[b,m,t] = sum_k W[m,k] * X[b,t,k]  (+bias, opt relu, opt mask-out)
// grid (TT/128, M/128, B), block 256 (8 warps as 2(M) x 4(N)), tiles 128x128x32
#define BM 128
#define BN 128
#define BK 32
#define ROWB 80                 // smem row stride bytes (32 bf16 = 64B data + 16B pad)
#define TSZ (128*ROWB)          // 10240 per tile
#define STG (4*TSZ)             // Ah, Al, Bh, Bl
#define GEMM_SMEM (2*STG)       // double buffered = 81920

__device__ __forceinline__ void load_stage(
    uint32_t sbase,
    const __nv_bfloat16* __restrict__ Whi, const __nv_bfloat16* __restrict__ Wlo,
    const __nv_bfloat16* __restrict__ Xhi, const __nv_bfloat16* __restrict__ Xlo,
    int K, int m0, size_t brow, int k0, int tid)
{
    #pragma unroll
    for (int i = 0; i < 2; ++i) {
        int s = tid + i*256;
        int row = s >> 2, seg = s & 3;
        uint32_t so = row*ROWB + seg*16;
        size_t ga = (size_t)(m0 + row)*K + k0 + seg*8;
        size_t gb = (brow + row)*K + k0 + seg*8;
        cpasync16(sbase +           so, Whi + ga);
        cpasync16(sbase +   TSZ +   so, Wlo + ga);
        cpasync16(sbase + 2*TSZ +   so, Xhi + gb);
        cpasync16(sbase + 3*TSZ +   so, Xlo + gb);
    }
}

template<bool RELU_, bool MOUT>
__global__ __launch_bounds__(256)
void gemm_mma(const __nv_bfloat16* __restrict__ Whi, const __nv_bfloat16* __restrict__ Wlo,
              const __nv_bfloat16* __restrict__ Xhi, const __nv_bfloat16* __restrict__ Xlo,
              const float* __restrict__ bias, const float* __restrict__ mask,
              float* __restrict__ Out, int M, int K)
{
    extern __shared__ char smem[];
    uint32_t sb = smem_u32(smem);
    int tid = threadIdx.x;
    int b  = blockIdx.z;
    int m0 = blockIdx.y * BM;
    int t0 = blockIdx.x * BN;
    size_t brow = (size_t)b*TT + t0;

    int w = tid >> 5, lane = tid & 31;
    int wm = w & 1, wn = w >> 1;

    float acc[4][4][4];
    #pragma unroll
    for (int i = 0; i < 4; ++i)
        #pragma unroll
        for (int j = 0; j < 4; ++j)
            #pragma unroll
            for (int q = 0; q < 4; ++q) acc[i][j][q] = 0.f;

    // ldmatrix per-lane base offsets
    uint32_t aoff = (uint32_t)(wm*64 + (lane & 15)) * ROWB + (uint32_t)(lane >> 4) * 16;
    uint32_t boff = (uint32_t)(wn*32 + (lane & 7))  * ROWB + (uint32_t)((lane >> 3) & 1) * 16;

    int nch = K / BK;
    load_stage(sb, Whi, Wlo, Xhi, Xlo, K, m0, brow, 0, tid);
    CP_COMMIT();

    for (int ch = 0; ch < nch; ++ch) {
        uint32_t cur = sb + (uint32_t)(ch & 1) * STG;
        if (ch + 1 < nch) {
            load_stage(sb + (uint32_t)((ch + 1) & 1) * STG,
                       Whi, Wlo, Xhi, Xlo, K, m0, brow, (ch + 1) * BK, tid);
            CP_COMMIT();
            CP_WAIT(1);
        } else {
            CP_WAIT(0);
        }
        __syncthreads();

        uint32_t sAh = cur, sAl = cur + TSZ, sBh = cur + 2*TSZ, sBl = cur + 3*TSZ;
        #pragma unroll
        for (int ks = 0; ks < 2; ++ks) {
            uint32_t Ah[4][4], Al[4][4], Bh[4][2], Bl[4][2];
            #pragma unroll
            for (int mi = 0; mi < 4; ++mi) {
                uint32_t o = aoff + (uint32_t)(mi*16)*ROWB + ks*32;
                ldmat4(Ah[mi], sAh + o);
                ldmat4(Al[mi], sAl + o);
            }
            #pragma unroll
            for (int ni = 0; ni < 4; ++ni) {
                uint32_t o = boff + (uint32_t)(ni*8)*ROWB + ks*32;
                ldmat2(Bh[ni], sBh + o);
                ldmat2(Bl[ni], sBl + o);
            }
            #pragma unroll
            for (int mi = 0; mi < 4; ++mi)
                #pragma unroll
                for (int ni = 0; ni < 4; ++ni) {
                    mma_bf16(acc[mi][ni], Ah[mi], Bh[ni]);
                    mma_bf16(acc[mi][ni], Ah[mi], Bl[ni]);
                    mma_bf16(acc[mi][ni], Al[mi], Bh[ni]);
                }
        }
        __syncthreads();
    }

    // ---- epilogue ----
    const float* mrow = mask + (size_t)b*TT + t0;
    #pragma unroll
    for (int mi = 0; mi < 4; ++mi) {
        int m = m0 + wm*64 + mi*16 + (lane >> 2);
        float bi0 = bias[m], bi1 = bias[m + 8];
        float* orow0 = Out + ((size_t)b*M + m)*TT + t0;
        float* orow1 = orow0 + (size_t)8*TT;
        #pragma unroll
        for (int ni = 0; ni < 4; ++ni) {
            int tc = wn*32 + ni*8 + (lane & 3)*2;
            float2 v0, v1;
            v0.x = acc[mi][ni][0] + bi0; v0.y = acc[mi][ni][1] + bi0;
            v1.x = acc[mi][ni][2] + bi1; v1.y = acc[mi][ni][3] + bi1;
            if (RELU_) {
                v0.x = fmaxf(v0.x, 0.f); v0.y = fmaxf(v0.y, 0.f);
                v1.x = fmaxf(v1.x, 0.f); v1.y = fmaxf(v1.y, 0.f);
            }
            if (MOUT) {
                float2 mo = *(const float2*)(mrow + tc);
                v0.x *= mo.x; v0.y *= mo.y;
                v1.x *= mo.x; v1.y *= mo.y;
            }
            *(float2*)(orow0 + tc) = v0;
            *(float2*)(orow1 + tc) = v1;
        }
    }
}

// ---------------- GLU: s4[b,o,t] = z[b,o,t] * sigmoid(z[b,o+H,t]) ----------------
__global__ void glu_kernel(const float* __restrict__ z, float* __restrict__ out)
{
    int idx = blockIdx.x * blockDim.x + threadIdx.x;
    if (idx >= BB*HH*TT) return;
    int t = idx % TT;
    int rem = idx / TT;
    int o = rem % HH;
    int b = rem / HH;
    float a = z[((size_t)b * (2*HH) + o) * TT + t];
    float g = z[((size_t)b * (2*HH) + o + HH) * TT + t];
    out[idx] = a / (1.0f + expf(-g));
}

// ---------------- channel LayerNorm with residual --------------------------------
template<bool MASK_RES, bool MASK_OUT>
__global__ __launch_bounds__(256)
void ln_kernel(const float* __restrict__ in1, const float* __restrict__ in2,
               const float* __restrict__ mask,
               const float* __restrict__ gamma, const float* __restrict__ beta,
               float* __restrict__ out)
{
    extern __shared__ float v[];            // [HH][64]
    __shared__ float rsum[4][64], rsq[4][64], mean_s[64], rstd_s[64];

    int b = blockIdx.y, t0 = blockIdx.x * 64, tid = threadIdx.x;
    const float* m = mask + (size_t)b * TT + t0;

    #pragma unroll 4
    for (int it = 0; it < (HH*64)/256; ++it) {
        int idx = it * 256 + tid;
        int h = idx >> 6, t = idx & 63;
        size_t g = ((size_t)(b*HH + h)) * TT + t0 + t;
        float a = in1[g];
        if (MASK_RES) a *= m[t];
        v[idx] = a + in2[g];
    }
    __syncthreads();

    int grp = tid >> 6, lt = tid & 63;
    float s = 0.f, q = 0.f;
    for (int h = grp*96; h < grp*96 + 96; ++h) {
        float w = v[h*64 + lt];
        s += w; q += w*w;
    }
    rsum[grp][lt] = s; rsq[grp][lt] = q;
    __syncthreads();
    if (grp == 0) {
        float ts = rsum[0][lt] + rsum[1][lt] + rsum[2][lt] + rsum[3][lt];
        float tq = rsq [0][lt] + rsq [1][lt] + rsq [2][lt] + rsq [3][lt];
        float mu = ts * (1.0f / HH);
        float var = tq * (1.0f / HH) - mu * mu;
        mean_s[lt] = mu;
        rstd_s[lt] = rsqrtf(var + 1e-4f);
    }
    __syncthreads();

    #pragma unroll 4
    for (int it = 0; it < (HH*64)/256; ++it) {
        int idx = it * 256 + tid;
        int h = idx >> 6, t = idx & 63;
        float w = (v[idx] - mean_s[t]) * rstd_s[t] * gamma[h] + beta[h];
        if (MASK_OUT) w *= m[t];
        out[((size_t)(b*HH + h)) * TT + t0 + t] = w;
    }
}

// ---------------- host launch -----------------------------------------------------
extern "C" void kernel_launch(void* const* d_in, const int* in_sizes, int n_in,
                              void* d_out, int out_size)
{
    (void)in_sizes; (void)n_in; (void)out_size;
    const float* x      = (const float*)d_in[0];
    const float* mask   = (const float*)d_in[1];
    const float* log_dt = (const float*)d_in[2];
    const float* A_re   = (const float*)d_in[3];
    const float* A_im   = (const float*)d_in[4];
    const float* C_re   = (const float*)d_in[5];
    const float* C_im   = (const float*)d_in[6];
    const float* Dp     = (const float*)d_in[7];
    const float* Wout   = (const float*)d_in[8];
    const float* bout   = (const float*)d_in[9];
    const float* g1     = (const float*)d_in[10];
    const float* be1    = (const float*)d_in[11];
    const float* W1     = (const float*)d_in[12];
    const float* bf1    = (const float*)d_in[13];
    const float* W2     = (const float*)d_in[14];
    const float* bf2    = (const float*)d_in[15];
    const float* g2     = (const float*)d_in[16];
    const float* be2    = (const float*)d_in[17];

    float *gy, *gs4, *gx1, *gxb, *gh1;
    __nv_bfloat16 *whi, *wlo, *xhi, *xlo;
    cudaGetSymbolAddress((void**)&gy,  g_y);
    cudaGetSymbolAddress((void**)&gs4, g_s4);
    cudaGetSymbolAddress((void**)&gx1, g_x1);
    cudaGetSymbolAddress((void**)&gxb, g_xb);
    cudaGetSymbolAddress((void**)&gh1, g_h1);
    cudaGetSymbolAddress((void**)&whi, g_whi);
    cudaGetSymbolAddress((void**)&wlo, g_wlo);
    cudaGetSymbolAddress((void**)&xhi, g_xhi);
    cudaGetSymbolAddress((void**)&xlo, g_xlo);

    const int LN_SMEM = HH * 64 * 4;
    cudaFuncSetAttribute(ln_kernel<true,  false>, cudaFuncAttributeMaxDynamicSharedMemorySize, LN_SMEM);
    cudaFuncSetAttribute(ln_kernel<false, false>, cudaFuncAttributeMaxDynamicSharedMemorySize, LN_SMEM);
    cudaFuncSetAttribute(ln_kernel<false, true >, cudaFuncAttributeMaxDynamicSharedMemorySize, LN_SMEM);
    cudaFuncSetAttribute(gemm_mma<false, false>, cudaFuncAttributeMaxDynamicSharedMemorySize, GEMM_SMEM);
    cudaFuncSetAttribute(gemm_mma<true,  false>, cudaFuncAttributeMaxDynamicSharedMemorySize, GEMM_SMEM);
    cudaFuncSetAttribute(gemm_mma<false, true >, cudaFuncAttributeMaxDynamicSharedMemorySize, GEMM_SMEM);

    const float* xcur = x;
    for (int l = 0; l < LYR; ++l) {
        // 1. S4D scan + D-skip + GELU -> g_y
        scan_kernel<<<(BB*HH)/4, 128>>>(xcur, mask, log_dt, A_re, A_im, C_re, C_im, Dp, gy, l);

        // 2. z = Wout @ y + bout   (M=768, K=384) -> g_h1
        convw_kernel<<<(2*HH*HH + 255)/256, 256>>>(Wout + (size_t)l*2*HH*HH, whi, wlo, 2*HH*HH);
        convx_kernel<false><<<dim3(TT/32, HH/32, BB), dim3(32, 8)>>>(gy, mask, xhi, xlo, HH);
        gemm_mma<false, false><<<dim3(TT/BN, (2*HH)/BM, BB), 256, GEMM_SMEM>>>(
            whi, wlo, xhi, xlo, bout + (size_t)l*2*HH, mask, gh1, 2*HH, HH);

        // 3. GLU -> g_s4
        glu_kernel<<<(BB*HH*TT + 255)/256, 256>>>(gh1, gs4);

        // 4. LN1( x*mask + s4 ) -> g_x1
        ln_kernel<true, false><<<dim3(TT/64, BB), 256, LN_SMEM>>>(
            xcur, gs4, mask, g1 + (size_t)l*HH, be1 + (size_t)l*HH, gx1);

        // 5. h = relu(W1 @ (x1*mask) + bf1)  (M=1536, K=384) -> g_h1
        convw_kernel<<<(HF*HH + 255)/256, 256>>>(W1 + (size_t)l*HF*HH, whi, wlo, HF*HH);
        convx_kernel<true><<<dim3(TT/32, HH/32, BB), dim3(32, 8)>>>(gx1, mask, xhi, xlo, HH);
        gemm_mma<true, false><<<dim3(TT/BN, HF/BM, BB), 256, GEMM_SMEM>>>(
            whi, wlo, xhi, xlo, bf1 + (size_t)l*HF, mask, gh1, HF, HH);

        // 6. o = (W2 @ (h*mask) + bf2) * mask  (M=384, K=1536) -> g_y
        convw_kernel<<<(HH*HF + 255)/256, 256>>>(W2 + (size_t)l*HH*HF, whi, wlo, HH*HF);
        convx_kernel<true><<<dim3(TT/32, HF/32, BB), dim3(32, 8)>>>(gh1, mask, xhi, xlo, HF);
        gemm_mma<false, true><<<dim3(TT/BN, HH/BM, BB), 256, GEMM_SMEM>>>(
            whi, wlo, xhi, xlo, bf2 + (size_t)l*HH, mask, gy, HH, HF);

        // 7. LN2( x1 + o ) -> next x (final layer: *mask into d_out)
        if (l == LYR - 1) {
            ln_kernel<false, true><<<dim3(TT/64, BB), 256, LN_SMEM>>>(
                gx1, gy, mask, g2 + (size_t)l*HH, be2 + (size_t)l*HH, (float*)d_out);
        } else {
            ln_kernel<false, false><<<dim3(TT/64, BB), 256, LN_SMEM>>>(
                gx1, gy, mask, g2 + (size_t)l*HH, be2 + (size_t)l*HH, gxb);
        }
        xcur = gxb;
    }
}

// round 5
// speedup vs baseline: 2.0907x; 1.5047x over previous
#include <cuda_runtime.h>
#include <cuda_bf16.h>
#include <math.h>
#include <stdint.h>

#define LYR 6
#define BB  16
#define HH  384
#define TT  2048
#define N2  32
#define HF  1536
#define NTOK (BB*TT)

// ---------------- scratch (device globals) ----------------------------------------
__device__ float g_a[(size_t)NTOK*HH];   // xcur [B,T,H] (layer in / LN2 out)
__device__ float g_b[(size_t)NTOK*HH];   // s4 / FFN out
__device__ float g_c[(size_t)NTOK*HH];   // x1 (LN1 out)
__device__ __nv_bfloat16 g_xhi[(size_t)NTOK*HH], g_xlo[(size_t)NTOK*HH]; // K=384 operand
__device__ __nv_bfloat16 g_hhi[(size_t)NTOK*HF], g_hlo[(size_t)NTOK*HF]; // K=1536 operand
__device__ __nv_bfloat16 g_wouth[LYR*2*HH*HH], g_woutl[LYR*2*HH*HH];     // GLU-permuted
__device__ __nv_bfloat16 g_w1h[LYR*HF*HH],  g_w1l[LYR*HF*HH];
__device__ __nv_bfloat16 g_w2h[LYR*HH*HF],  g_w2l[LYR*HH*HF];

// ================= helpers =================
__device__ __forceinline__ uint32_t smem_u32(const void* p) {
    uint32_t a;
    asm("{ .reg .u64 t; cvta.to.shared.u64 t, %1; cvt.u32.u64 %0, t; }" : "=r"(a) : "l"(p));
    return a;
}
__device__ __forceinline__ void cpasync16(uint32_t saddr, const void* g) {
    asm volatile("cp.async.cg.shared.global [%0], [%1], 16;" :: "r"(saddr), "l"(g));
}
#define CP_COMMIT() asm volatile("cp.async.commit_group;" ::: "memory")
#define CP_WAIT(n)  asm volatile("cp.async.wait_group %0;" :: "n"(n) : "memory")

__device__ __forceinline__ void ldmat4(uint32_t* r, uint32_t a) {
    asm volatile("ldmatrix.sync.aligned.m8n8.x4.shared.b16 {%0,%1,%2,%3}, [%4];"
        : "=r"(r[0]), "=r"(r[1]), "=r"(r[2]), "=r"(r[3]) : "r"(a));
}
__device__ __forceinline__ void ldmat2(uint32_t* r, uint32_t a) {
    asm volatile("ldmatrix.sync.aligned.m8n8.x2.shared.b16 {%0,%1}, [%2];"
        : "=r"(r[0]), "=r"(r[1]) : "r"(a));
}
__device__ __forceinline__ void mma_bf16(float* d, const uint32_t* a, const uint32_t* b) {
    asm volatile("mma.sync.aligned.m16n8k16.row.col.f32.bf16.bf16.f32 "
        "{%0,%1,%2,%3}, {%4,%5,%6,%7}, {%8,%9}, {%0,%1,%2,%3};"
        : "+f"(d[0]), "+f"(d[1]), "+f"(d[2]), "+f"(d[3])
        : "r"(a[0]), "r"(a[1]), "r"(a[2]), "r"(a[3]), "r"(b[0]), "r"(b[1]));
}
__device__ __forceinline__ uint32_t bf2u(__nv_bfloat162 v) {
    return *reinterpret_cast<uint32_t*>(&v);
}

// ---------------- weight conversion (once per call, all layers) --------------------
__global__ void convw_plain(const float* __restrict__ W,
                            __nv_bfloat16* __restrict__ hi, __nv_bfloat16* __restrict__ lo,
                            int n)
{
    int i = blockIdx.x * blockDim.x + threadIdx.x;
    if (i >= n) return;
    float w = W[i];
    __nv_bfloat16 h = __float2bfloat16(w);
    hi[i] = h;
    lo[i] = __float2bfloat16(w - __bfloat162float(h));
}

// Wout with GLU row permutation: dest row r -> src row (r&1) ? HH + r/2 : r/2
__global__ void convw_perm(const float* __restrict__ W,
                           __nv_bfloat16* __restrict__ hi, __nv_bfloat16* __restrict__ lo)
{
    int i = blockIdx.x * blockDim.x + threadIdx.x;
    if (i >= LYR*2*HH*HH) return;
    int k = i % HH;
    int rr = i / HH;
    int r = rr % (2*HH);
    int l = rr / (2*HH);
    int src = (r & 1) ? (HH + (r >> 1)) : (r >> 1);
    float w = W[((size_t)l*2*HH + src)*HH + k];
    __nv_bfloat16 h = __float2bfloat16(w);
    hi[i] = h;
    lo[i] = __float2bfloat16(w - __bfloat162float(h));
}

// ---------------- transposes ------------------------------------------------------
// in [B,H,T] -> out [B,T,H]
__global__ void transpose_in(const float* __restrict__ in, float* __restrict__ out)
{
    __shared__ float tile[32][33];
    int b = blockIdx.z, t0 = blockIdx.x*32, h0 = blockIdx.y*32;
    int tx = threadIdx.x, ty = threadIdx.y;
    #pragma unroll
    for (int i = 0; i < 4; ++i)
        tile[ty + i*8][tx] = in[((size_t)b*HH + h0 + ty + i*8)*TT + t0 + tx];
    __syncthreads();
    #pragma unroll
    for (int i = 0; i < 4; ++i)
        out[((size_t)b*TT + t0 + ty + i*8)*HH + h0 + tx] = tile[tx][ty + i*8];
}
// in [B,T,H] -> out [B,H,T], * mask[b][t]
__global__ void transpose_out(const float* __restrict__ in, const float* __restrict__ mask,
                              float* __restrict__ out)
{
    __shared__ float tile[32][33];
    int b = blockIdx.z, t0 = blockIdx.x*32, h0 = blockIdx.y*32;
    int tx = threadIdx.x, ty = threadIdx.y;
    #pragma unroll
    for (int i = 0; i < 4; ++i)
        tile[ty + i*8][tx] = in[((size_t)b*TT + t0 + ty + i*8)*HH + h0 + tx];
    __syncthreads();
    float mv = mask[(size_t)b*TT + t0 + tx];
    #pragma unroll
    for (int i = 0; i < 4; ++i)
        out[((size_t)b*HH + h0 + ty + i*8)*TT + t0 + tx] = tile[tx][ty + i*8] * mv;
}

// ---------------- S4D scan (smem-transpose reduce), writes bf16 hi/lo [B,T,H] -----
__global__ __launch_bounds__(128)
void scan_kernel(const float* __restrict__ x, const float* __restrict__ mask,
                 const float* __restrict__ log_dt,
                 const float* __restrict__ A_re, const float* __restrict__ A_im,
                 const float* __restrict__ C_re, const float* __restrict__ C_im,
                 const float* __restrict__ Dp,
                 __nv_bfloat16* __restrict__ yhi, __nv_bfloat16* __restrict__ ylo, int layer)
{
    __shared__ float sx[4][33];
    __shared__ float sc[4][32][33];
    int w = threadIdx.x >> 5, lane = threadIdx.x & 31;
    int wid = blockIdx.x*4 + w;
    int b = wid / HH, h = wid % HH;

    float dt = expf(log_dt[layer*HH + h]);
    int pidx = (layer*HH + h) * N2 + lane;
    float ar = A_re[pidx], ai = A_im[pidx];
    float dre = ar * dt, dim = ai * dt;
    float e   = expf(dre);
    float wre = e * cosf(dim);
    float wim = e * sinf(dim);
    float nre = wre - 1.0f, nim = wim;
    float d2  = ar*ar + ai*ai;
    float qre = (nre*ar + nim*ai) / d2;
    float qim = (nim*ar - nre*ai) / d2;
    float cre = C_re[pidx], cim = C_im[pidx];
    float cdre = cre*qre - cim*qim;
    float cdim = cre*qim + cim*qre;
    float Dv = Dp[layer*HH + h];

    const float* mr = mask + (size_t)b * TT;
    float sre = 0.f, sim = 0.f;

    for (int c = 0; c < TT/32; ++c) {
        int t0 = c*32;
        float xv = x[((size_t)b*TT + t0 + lane)*HH + h] * mr[t0 + lane];
        sx[w][lane] = xv;
        __syncwarp();
        const float* sxr = sx[w];
        #pragma unroll
        for (int j = 0; j < 32; ++j) {
            float xj = sxr[j];
            float tre = fmaf(wre, sre, fmaf(-wim, sim, xj));
            float tim = fmaf(wre, sim, wim * sre);
            sre = tre; sim = tim;
            sc[w][lane][j] = fmaf(cdre, sre, -cdim * sim);
        }
        __syncwarp();
        float sum = 0.f;
        #pragma unroll
        for (int n = 0; n < 32; ++n) sum += sc[w][n][lane];
        float yv = 2.0f*sum + Dv * sxr[lane];
        yv = 0.5f * yv * (1.0f + erff(yv * 0.70710678118654752f));
        __nv_bfloat16 hv = __float2bfloat16(yv);
        size_t o = ((size_t)b*TT + t0 + lane)*HH + h;
        yhi[o] = hv;
        ylo[o] = __float2bfloat16(yv - __bfloat162float(hv));
        __syncwarp();
    }
}

// ---------------- split-bf16 mma.sync GEMM with fused transposed epilogues ---------
#define BM 128
#define BN 128
#define BK 32
#define ROWB 80
#define TSZ (128*ROWB)
#define STG (4*TSZ)
#define NSTAGE 3
#define GEMM_SMEM (NSTAGE*STG)   // 122880 >= epilogue tile 128*132*4

#define EPI_GLU  0
#define EPI_HILO 1
#define EPI_FP32 2

__device__ __forceinline__ void load_stage(
    uint32_t sbase,
    const __nv_bfloat16* __restrict__ Whi, const __nv_bfloat16* __restrict__ Wlo,
    const __nv_bfloat16* __restrict__ Xhi, const __nv_bfloat16* __restrict__ Xlo,
    int K, int m0, size_t brow, int k0, int tid)
{
    #pragma unroll
    for (int i = 0; i < 2; ++i) {
        int s = tid + i*256;
        int row = s >> 2, seg = s & 3;
        uint32_t so = row*ROWB + seg*16;
        size_t ga = (size_t)(m0 + row)*K + k0 + seg*8;
        size_t gb = (brow + row)*K + k0 + seg*8;
        cpasync16(sbase +           so, Whi + ga);
        cpasync16(sbase +   TSZ +   so, Wlo + ga);
        cpasync16(sbase + 2*TSZ +   so, Xhi + gb);
        cpasync16(sbase + 3*TSZ +   so, Xlo + gb);
    }
}

template<int EPI>
__global__ __launch_bounds__(256)
void gemm_mma(const __nv_bfloat16* __restrict__ Whi, const __nv_bfloat16* __restrict__ Wlo,
              const __nv_bfloat16* __restrict__ Xhi, const __nv_bfloat16* __restrict__ Xlo,
              const float* __restrict__ bias, const float* __restrict__ mask,
              float* __restrict__ OutF,
              __nv_bfloat16* __restrict__ OutHi, __nv_bfloat16* __restrict__ OutLo,
              int K, int ldo)
{
    extern __shared__ char smem[];
    uint32_t sb = smem_u32(smem);
    int tid = threadIdx.x;
    int b  = blockIdx.z;
    int m0 = blockIdx.y * BM;
    int t0 = blockIdx.x * BN;
    size_t brow = (size_t)b*TT + t0;

    int w = tid >> 5, lane = tid & 31;
    int wm = w & 1, wn = w >> 1;

    float acc[4][4][4];
    #pragma unroll
    for (int i = 0; i < 4; ++i)
        #pragma unroll
        for (int j = 0; j < 4; ++j)
            #pragma unroll
            for (int q = 0; q < 4; ++q) acc[i][j][q] = 0.f;

    uint32_t aoff = (uint32_t)(wm*64 + (lane & 15)) * ROWB + (uint32_t)(lane >> 4) * 16;
    uint32_t boff = (uint32_t)(wn*32 + (lane & 7))  * ROWB + (uint32_t)((lane >> 3) & 1) * 16;

    int nch = K / BK;
    load_stage(sb, Whi, Wlo, Xhi, Xlo, K, m0, brow, 0, tid);
    CP_COMMIT();
    load_stage(sb + STG, Whi, Wlo, Xhi, Xlo, K, m0, brow, BK, tid);
    CP_COMMIT();

    for (int ch = 0; ch < nch; ++ch) {
        CP_WAIT(1);
        __syncthreads();
        if (ch + 2 < nch)
            load_stage(sb + (uint32_t)((ch + 2) % NSTAGE) * STG,
                       Whi, Wlo, Xhi, Xlo, K, m0, brow, (ch + 2) * BK, tid);
        CP_COMMIT();

        uint32_t cur = sb + (uint32_t)(ch % NSTAGE) * STG;
        uint32_t sAh = cur, sAl = cur + TSZ, sBh = cur + 2*TSZ, sBl = cur + 3*TSZ;
        #pragma unroll
        for (int ks = 0; ks < 2; ++ks) {
            uint32_t Ah[4][4], Al[4][4], Bh[4][2], Bl[4][2];
            #pragma unroll
            for (int mi = 0; mi < 4; ++mi) {
                uint32_t o = aoff + (uint32_t)(mi*16)*ROWB + ks*32;
                ldmat4(Ah[mi], sAh + o);
                ldmat4(Al[mi], sAl + o);
            }
            #pragma unroll
            for (int ni = 0; ni < 4; ++ni) {
                uint32_t o = boff + (uint32_t)(ni*8)*ROWB + ks*32;
                ldmat2(Bh[ni], sBh + o);
                ldmat2(Bl[ni], sBl + o);
            }
            #pragma unroll
            for (int mi = 0; mi < 4; ++mi)
                #pragma unroll
                for (int ni = 0; ni < 4; ++ni) {
                    mma_bf16(acc[mi][ni], Ah[mi], Bh[ni]);
                    mma_bf16(acc[mi][ni], Ah[mi], Bl[ni]);
                    mma_bf16(acc[mi][ni], Al[mi], Bh[ni]);
                }
        }
        __syncthreads();   // all warps done with stage ch before its buffer is refilled
    }
    CP_WAIT(0);
    __syncthreads();

    // ---- stage fragments to smem as [t][m] (132-float padded rows) ----
    float* smemf = (float*)smem;
    #pragma unroll
    for (int mi = 0; mi < 4; ++mi) {
        int ma = wm*64 + mi*16 + (lane >> 2);
        #pragma unroll
        for (int ni = 0; ni < 4; ++ni) {
            int tc = wn*32 + ni*8 + (lane & 3)*2;
            float* st = smemf + tc*132;
            st[ma]        = acc[mi][ni][0];
            st[132 + ma]  = acc[mi][ni][1];
            st[ma + 8]    = acc[mi][ni][2];
            st[132 + ma + 8] = acc[mi][ni][3];
        }
    }
    __syncthreads();

    // ---- write phase: coalesced channel-major output -------------------------
    if (EPI == EPI_GLU) {
        int m = lane*4;
        // permuted bias: dest z-row r: even -> bout[r/2], odd -> bout[HH + r/2]
        int r0 = m0 + m;
        float b0a = bias[(r0&1)?(HH+(r0>>1)):(r0>>1)];
        float b0g = bias[((r0+1)&1)?(HH+((r0+1)>>1)):((r0+1)>>1)];
        float b1a = bias[((r0+2)&1)?(HH+((r0+2)>>1)):((r0+2)>>1)];
        float b1g = bias[((r0+3)&1)?(HH+((r0+3)>>1)):((r0+3)>>1)];
        #pragma unroll
        for (int p = 0; p < 16; ++p) {
            int r = p*8 + (tid >> 5);
            float4 z = *(float4*)(smemf + r*132 + m);
            float a0 = z.x + b0a, gg0 = z.y + b0g;
            float a1 = z.z + b1a, gg1 = z.w + b1g;
            float2 s;
            s.x = a0 / (1.0f + expf(-gg0));
            s.y = a1 / (1.0f + expf(-gg1));
            *(float2*)(OutF + ((size_t)b*TT + t0 + r)*HH + (m0>>1) + lane*2) = s;
        }
    } else if (EPI == EPI_HILO) {
        int m = lane*4;
        float4 bi = *(const float4*)(bias + m0 + m);
        #pragma unroll
        for (int p = 0; p < 16; ++p) {
            int r = p*8 + (tid >> 5);
            float mv = mask[(size_t)b*TT + t0 + r];
            float4 v = *(float4*)(smemf + r*132 + m);
            v.x = fmaxf(v.x + bi.x, 0.f) * mv;
            v.y = fmaxf(v.y + bi.y, 0.f) * mv;
            v.z = fmaxf(v.z + bi.z, 0.f) * mv;
            v.w = fmaxf(v.w + bi.w, 0.f) * mv;
            __nv_bfloat162 h0 = __floats2bfloat162_rn(v.x, v.y);
            __nv_bfloat162 h1 = __floats2bfloat162_rn(v.z, v.w);
            __nv_bfloat162 l0 = __floats2bfloat162_rn(v.x - __bfloat162float(h0.x),
                                                      v.y - __bfloat162float(h0.y));
            __nv_bfloat162 l1 = __floats2bfloat162_rn(v.z - __bfloat162float(h1.x),
                                                      v.w - __bfloat162float(h1.y));
            size_t o = ((size_t)b*TT + t0 + r)*ldo + m0 + m;
            *(uint2*)(OutHi + o) = make_uint2(bf2u(h0), bf2u(h1));
            *(uint2*)(OutLo + o) = make_uint2(bf2u(l0), bf2u(l1));
        }
    } else {
        int m = lane*4;
        float4 bi = *(const float4*)(bias + m0 + m);
        #pragma unroll
        for (int p = 0; p < 16; ++p) {
            int r = p*8 + (tid >> 5);
            float mv = mask[(size_t)b*TT + t0 + r];
            float4 v = *(float4*)(smemf + r*132 + m);
            v.x = (v.x + bi.x) * mv;
            v.y = (v.y + bi.y) * mv;
            v.z = (v.z + bi.z) * mv;
            v.w = (v.w + bi.w) * mv;
            *(float4*)(OutF + ((size_t)b*TT + t0 + r)*HH + m0 + m) = v;
        }
    }
}

// ---------------- channel LayerNorm (channels contiguous), warp per token ---------
// MODE 0: v = res*mask + y; write x1 fp32 + bf16 hi/lo of (x1*mask)
// MODE 1: v = res + y;      write fp32 only
template<int MODE>
__global__ __launch_bounds__(256)
void ln_kernel(const float* __restrict__ res, const float* __restrict__ yy,
               const float* __restrict__ mask,
               const float* __restrict__ gamma, const float* __restrict__ beta,
               float* __restrict__ outF,
               __nv_bfloat16* __restrict__ outHi, __nv_bfloat16* __restrict__ outLo)
{
    int g = blockIdx.x*8 + (threadIdx.x >> 5);
    int lane = threadIdx.x & 31;
    size_t base = (size_t)g*HH;
    float mv = mask[g];

    float4 v[3];
    float s = 0.f, q = 0.f;
    #pragma unroll
    for (int j = 0; j < 3; ++j) {
        float4 r1 = *(const float4*)(res + base + lane*4 + j*128);
        float4 r2 = *(const float4*)(yy  + base + lane*4 + j*128);
        float4 t;
        if (MODE == 0) {
            t.x = fmaf(r1.x, mv, r2.x); t.y = fmaf(r1.y, mv, r2.y);
            t.z = fmaf(r1.z, mv, r2.z); t.w = fmaf(r1.w, mv, r2.w);
        } else {
            t.x = r1.x + r2.x; t.y = r1.y + r2.y;
            t.z = r1.z + r2.z; t.w = r1.w + r2.w;
        }
        v[j] = t;
        s += t.x + t.y + t.z + t.w;
        q += t.x*t.x + t.y*t.y + t.z*t.z + t.w*t.w;
    }
    #pragma unroll
    for (int off = 16; off; off >>= 1) {
        s += __shfl_xor_sync(0xffffffffu, s, off);
        q += __shfl_xor_sync(0xffffffffu, q, off);
    }
    float mu = s * (1.0f/HH);
    float rs = rsqrtf(q * (1.0f/HH) - mu*mu + 1e-4f);

    #pragma unroll
    for (int j = 0; j < 3; ++j) {
        float4 ga = *(const float4*)(gamma + lane*4 + j*128);
        float4 be = *(const float4*)(beta  + lane*4 + j*128);
        float4 t = v[j];
        t.x = (t.x - mu)*rs*ga.x + be.x;
        t.y = (t.y - mu)*rs*ga.y + be.y;
        t.z = (t.z - mu)*rs*ga.z + be.z;
        t.w = (t.w - mu)*rs*ga.w + be.w;
        *(float4*)(outF + base + lane*4 + j*128) = t;
        if (MODE == 0) {
            t.x *= mv; t.y *= mv; t.z *= mv; t.w *= mv;
            __nv_bfloat162 h0 = __floats2bfloat162_rn(t.x, t.y);
            __nv_bfloat162 h1 = __floats2bfloat162_rn(t.z, t.w);
            __nv_bfloat162 l0 = __floats2bfloat162_rn(t.x - __bfloat162float(h0.x),
                                                      t.y - __bfloat162float(h0.y));
            __nv_bfloat162 l1 = __floats2bfloat162_rn(t.z - __bfloat162float(h1.x),
                                                      t.w - __bfloat162float(h1.y));
            *(uint2*)(outHi + base + lane*4 + j*128) = make_uint2(bf2u(h0), bf2u(h1));
            *(uint2*)(outLo + base + lane*4 + j*128) = make_uint2(bf2u(l0), bf2u(l1));
        }
    }
}

// ---------------- host launch -----------------------------------------------------
extern "C" void kernel_launch(void* const* d_in, const int* in_sizes, int n_in,
                              void* d_out, int out_size)
{
    (void)in_sizes; (void)n_in; (void)out_size;
    const float* x      = (const float*)d_in[0];
    const float* mask   = (const float*)d_in[1];
    const float* log_dt = (const float*)d_in[2];
    const float* A_re   = (const float*)d_in[3];
    const float* A_im   = (const float*)d_in[4];
    const float* C_re   = (const float*)d_in[5];
    const float* C_im   = (const float*)d_in[6];
    const float* Dp     = (const float*)d_in[7];
    const float* Wout   = (const float*)d_in[8];
    const float* bout   = (const float*)d_in[9];
    const float* g1     = (const float*)d_in[10];
    const float* be1    = (const float*)d_in[11];
    const float* W1     = (const float*)d_in[12];
    const float* bf1    = (const float*)d_in[13];
    const float* W2     = (const float*)d_in[14];
    const float* bf2    = (const float*)d_in[15];
    const float* g2     = (const float*)d_in[16];
    const float* be2    = (const float*)d_in[17];

    float *ga, *gb, *gc;
    __nv_bfloat16 *xhi, *xlo, *hhi, *hlo, *wouth, *woutl, *w1h, *w1l, *w2h, *w2l;
    cudaGetSymbolAddress((void**)&ga, g_a);
    cudaGetSymbolAddress((void**)&gb, g_b);
    cudaGetSymbolAddress((void**)&gc, g_c);
    cudaGetSymbolAddress((void**)&xhi, g_xhi);
    cudaGetSymbolAddress((void**)&xlo, g_xlo);
    cudaGetSymbolAddress((void**)&hhi, g_hhi);
    cudaGetSymbolAddress((void**)&hlo, g_hlo);
    cudaGetSymbolAddress((void**)&wouth, g_wouth);
    cudaGetSymbolAddress((void**)&woutl, g_woutl);
    cudaGetSymbolAddress((void**)&w1h, g_w1h);
    cudaGetSymbolAddress((void**)&w1l, g_w1l);
    cudaGetSymbolAddress((void**)&w2h, g_w2h);
    cudaGetSymbolAddress((void**)&w2l, g_w2l);

    cudaFuncSetAttribute(gemm_mma<EPI_GLU >, cudaFuncAttributeMaxDynamicSharedMemorySize, GEMM_SMEM);
    cudaFuncSetAttribute(gemm_mma<EPI_HILO>, cudaFuncAttributeMaxDynamicSharedMemorySize, GEMM_SMEM);
    cudaFuncSetAttribute(gemm_mma<EPI_FP32>, cudaFuncAttributeMaxDynamicSharedMemorySize, GEMM_SMEM);

    // weight conversion (all layers, once)
    convw_perm <<<(LYR*2*HH*HH + 255)/256, 256>>>(Wout, wouth, woutl);
    convw_plain<<<(LYR*HF*HH   + 255)/256, 256>>>(W1, w1h, w1l, LYR*HF*HH);
    convw_plain<<<(LYR*HH*HF   + 255)/256, 256>>>(W2, w2h, w2l, LYR*HH*HF);

    // input to [B,T,H]
    transpose_in<<<dim3(TT/32, HH/32, BB), dim3(32, 8)>>>(x, ga);

    for (int l = 0; l < LYR; ++l) {
        // 1. scan -> bf16 hi/lo [B,T,H]
        scan_kernel<<<(BB*HH)/4, 128>>>(ga, mask, log_dt, A_re, A_im, C_re, C_im, Dp,
                                        xhi, xlo, l);
        // 2. Wout GEMM + fused GLU -> s4 fp32 [B,T,H] (g_b)
        gemm_mma<EPI_GLU><<<dim3(TT/BN, (2*HH)/BM, BB), 256, GEMM_SMEM>>>(
            wouth + (size_t)l*2*HH*HH, woutl + (size_t)l*2*HH*HH, xhi, xlo,
            bout + (size_t)l*2*HH, mask, gb, nullptr, nullptr, HH, 0);
        // 3. LN1 -> x1 fp32 (g_c) + bf16 hi/lo of x1*mask
        ln_kernel<0><<<NTOK/8, 256>>>(ga, gb, mask, g1 + (size_t)l*HH, be1 + (size_t)l*HH,
                                      gc, xhi, xlo);
        // 4. W1 GEMM + relu + mask -> bf16 hi/lo [B,T,HF]
        gemm_mma<EPI_HILO><<<dim3(TT/BN, HF/BM, BB), 256, GEMM_SMEM>>>(
            w1h + (size_t)l*HF*HH, w1l + (size_t)l*HF*HH, xhi, xlo,
            bf1 + (size_t)l*HF, mask, nullptr, hhi, hlo, HH, HF);
        // 5. W2 GEMM + mask -> o fp32 [B,T,H] (g_b)
        gemm_mma<EPI_FP32><<<dim3(TT/BN, HH/BM, BB), 256, GEMM_SMEM>>>(
            w2h + (size_t)l*HH*HF, w2l + (size_t)l*HH*HF, hhi, hlo,
            bf2 + (size_t)l*HH, mask, gb, nullptr, nullptr, HF, 0);
        // 6. LN2 -> next x fp32 (g_a)
        ln_kernel<1><<<NTOK/8, 256>>>(gc, gb, mask, g2 + (size_t)l*HH, be2 + (size_t)l*HH,
                                      ga, nullptr, nullptr);
    }
    // final: [B,T,H] -> [B,H,T] * mask
    transpose_out<<<dim3(TT/32, HH/32, BB), dim3(32, 8)>>>(ga, mask, (float*)d_out);
}

// round 7
// speedup vs baseline: 2.3885x; 1.1424x over previous
#include <cuda_runtime.h>
#include <cuda_bf16.h>
#include <math.h>
#include <stdint.h>

#define LYR 6
#define BB  16
#define HH  384
#define TT  2048
#define N2  32
#define HF  1536
#define NTOK (BB*TT)

// ---------------- scratch (device globals) ----------------------------------------
__device__ float g_a[(size_t)NTOK*HH];   // xcur [B,T,H] (layer in / LN2 out)
__device__ float g_b[(size_t)NTOK*HH];   // s4 / FFN out
__device__ float g_c[(size_t)NTOK*HH];   // x1 (LN1 out)
__device__ __nv_bfloat16 g_xhi[(size_t)NTOK*HH], g_xlo[(size_t)NTOK*HH]; // K=384 operand
__device__ __nv_bfloat16 g_hhi[(size_t)NTOK*HF], g_hlo[(size_t)NTOK*HF]; // K=1536 operand
__device__ __nv_bfloat16 g_wouth[LYR*2*HH*HH], g_woutl[LYR*2*HH*HH];     // GLU-permuted
__device__ __nv_bfloat16 g_w1h[LYR*HF*HH],  g_w1l[LYR*HF*HH];
__device__ __nv_bfloat16 g_w2h[LYR*HH*HF],  g_w2l[LYR*HH*HF];

// ================= helpers =================
__device__ __forceinline__ uint32_t smem_u32(const void* p) {
    uint32_t a;
    asm("{ .reg .u64 t; cvta.to.shared.u64 t, %1; cvt.u32.u64 %0, t; }" : "=r"(a) : "l"(p));
    return a;
}
__device__ __forceinline__ void cpasync16(uint32_t saddr, const void* g) {
    asm volatile("cp.async.cg.shared.global [%0], [%1], 16;" :: "r"(saddr), "l"(g));
}
#define CP_COMMIT() asm volatile("cp.async.commit_group;" ::: "memory")
#define CP_WAIT(n)  asm volatile("cp.async.wait_group %0;" :: "n"(n) : "memory")

__device__ __forceinline__ void ldmat4(uint32_t* r, uint32_t a) {
    asm volatile("ldmatrix.sync.aligned.m8n8.x4.shared.b16 {%0,%1,%2,%3}, [%4];"
        : "=r"(r[0]), "=r"(r[1]), "=r"(r[2]), "=r"(r[3]) : "r"(a));
}
__device__ __forceinline__ void ldmat2(uint32_t* r, uint32_t a) {
    asm volatile("ldmatrix.sync.aligned.m8n8.x2.shared.b16 {%0,%1}, [%2];"
        : "=r"(r[0]), "=r"(r[1]) : "r"(a));
}
__device__ __forceinline__ void mma_bf16(float* d, const uint32_t* a, const uint32_t* b) {
    asm volatile("mma.sync.aligned.m16n8k16.row.col.f32.bf16.bf16.f32 "
        "{%0,%1,%2,%3}, {%4,%5,%6,%7}, {%8,%9}, {%0,%1,%2,%3};"
        : "+f"(d[0]), "+f"(d[1]), "+f"(d[2]), "+f"(d[3])
        : "r"(a[0]), "r"(a[1]), "r"(a[2]), "r"(a[3]), "r"(b[0]), "r"(b[1]));
}
__device__ __forceinline__ uint32_t bf2u(__nv_bfloat162 v) {
    return *reinterpret_cast<uint32_t*>(&v);
}

// ---------------- weight conversion (once per call, all layers) --------------------
__global__ void convw_plain(const float* __restrict__ W,
                            __nv_bfloat16* __restrict__ hi, __nv_bfloat16* __restrict__ lo,
                            int n)
{
    int i = blockIdx.x * blockDim.x + threadIdx.x;
    if (i >= n) return;
    float w = W[i];
    __nv_bfloat16 h = __float2bfloat16(w);
    hi[i] = h;
    lo[i] = __float2bfloat16(w - __bfloat162float(h));
}

// Wout with GLU row permutation: dest row r -> src row (r&1) ? HH + r/2 : r/2
__global__ void convw_perm(const float* __restrict__ W,
                           __nv_bfloat16* __restrict__ hi, __nv_bfloat16* __restrict__ lo)
{
    int i = blockIdx.x * blockDim.x + threadIdx.x;
    if (i >= LYR*2*HH*HH) return;
    int k = i % HH;
    int rr = i / HH;
    int r = rr % (2*HH);
    int l = rr / (2*HH);
    int src = (r & 1) ? (HH + (r >> 1)) : (r >> 1);
    float w = W[((size_t)l*2*HH + src)*HH + k];
    __nv_bfloat16 h = __float2bfloat16(w);
    hi[i] = h;
    lo[i] = __float2bfloat16(w - __bfloat162float(h));
}

// ---------------- transposes ------------------------------------------------------
__global__ void transpose_in(const float* __restrict__ in, float* __restrict__ out)
{
    __shared__ float tile[32][33];
    int b = blockIdx.z, t0 = blockIdx.x*32, h0 = blockIdx.y*32;
    int tx = threadIdx.x, ty = threadIdx.y;
    #pragma unroll
    for (int i = 0; i < 4; ++i)
        tile[ty + i*8][tx] = in[((size_t)b*HH + h0 + ty + i*8)*TT + t0 + tx];
    __syncthreads();
    #pragma unroll
    for (int i = 0; i < 4; ++i)
        out[((size_t)b*TT + t0 + ty + i*8)*HH + h0 + tx] = tile[tx][ty + i*8];
}
__global__ void transpose_out(const float* __restrict__ in, const float* __restrict__ mask,
                              float* __restrict__ out)
{
    __shared__ float tile[32][33];
    int b = blockIdx.z, t0 = blockIdx.x*32, h0 = blockIdx.y*32;
    int tx = threadIdx.x, ty = threadIdx.y;
    #pragma unroll
    for (int i = 0; i < 4; ++i)
        tile[ty + i*8][tx] = in[((size_t)b*TT + t0 + ty + i*8)*HH + h0 + tx];
    __syncthreads();
    float mv = mask[(size_t)b*TT + t0 + tx];
    #pragma unroll
    for (int i = 0; i < 4; ++i)
        out[((size_t)b*HH + h0 + ty + i*8)*TT + t0 + tx] = tile[tx][ty + i*8] * mv;
}

// ---------------- S4D scan (smem-transpose reduce), writes bf16 hi/lo [B,T,H] -----
__global__ __launch_bounds__(128)
void scan_kernel(const float* __restrict__ x, const float* __restrict__ mask,
                 const float* __restrict__ log_dt,
                 const float* __restrict__ A_re, const float* __restrict__ A_im,
                 const float* __restrict__ C_re, const float* __restrict__ C_im,
                 const float* __restrict__ Dp,
                 __nv_bfloat16* __restrict__ yhi, __nv_bfloat16* __restrict__ ylo, int layer)
{
    __shared__ float sx[4][33];
    __shared__ float sc[4][32][33];
    int w = threadIdx.x >> 5, lane = threadIdx.x & 31;
    int wid = blockIdx.x*4 + w;
    int b = wid / HH, h = wid % HH;

    float dt = expf(log_dt[layer*HH + h]);
    int pidx = (layer*HH + h) * N2 + lane;
    float ar = A_re[pidx], ai = A_im[pidx];
    float dre = ar * dt, dim = ai * dt;
    float e   = expf(dre);
    float wre = e * cosf(dim);
    float wim = e * sinf(dim);
    float nre = wre - 1.0f, nim = wim;
    float d2  = ar*ar + ai*ai;
    float qre = (nre*ar + nim*ai) / d2;
    float qim = (nim*ar - nre*ai) / d2;
    float cre = C_re[pidx], cim = C_im[pidx];
    float cdre = cre*qre - cim*qim;
    float cdim = cre*qim + cim*qre;
    float Dv = Dp[layer*HH + h];

    const float* mr = mask + (size_t)b * TT;
    float sre = 0.f, sim = 0.f;

    for (int c = 0; c < TT/32; ++c) {
        int t0 = c*32;
        float xv = x[((size_t)b*TT + t0 + lane)*HH + h] * mr[t0 + lane];
        sx[w][lane] = xv;
        __syncwarp();
        const float* sxr = sx[w];
        #pragma unroll
        for (int j = 0; j < 32; ++j) {
            float xj = sxr[j];
            float tre = fmaf(wre, sre, fmaf(-wim, sim, xj));
            float tim = fmaf(wre, sim, wim * sre);
            sre = tre; sim = tim;
            sc[w][lane][j] = fmaf(cdre, sre, -cdim * sim);
        }
        __syncwarp();
        float sum = 0.f;
        #pragma unroll
        for (int n = 0; n < 32; ++n) sum += sc[w][n][lane];
        float yv = 2.0f*sum + Dv * sxr[lane];
        yv = 0.5f * yv * (1.0f + erff(yv * 0.70710678118654752f));
        __nv_bfloat16 hv = __float2bfloat16(yv);
        size_t o = ((size_t)b*TT + t0 + lane)*HH + h;
        yhi[o] = hv;
        ylo[o] = __float2bfloat16(yv - __bfloat162float(hv));
        __syncwarp();
    }
}

// ---------------- split-bf16 mma.sync GEMM with fused transposed epilogues ---------
#define BM 128
#define BN 128
#define BK 32
#define ROWB 80
#define TSZ (128*ROWB)
#define STG (4*TSZ)
#define NSTAGE 2
#define GEMM_SMEM (NSTAGE*STG)   // 81920 >= epilogue tile 128*132*4 = 67584

#define EPI_GLU  0
#define EPI_HILO 1
#define EPI_FP32 2

__device__ __forceinline__ void load_stage(
    uint32_t sbase,
    const __nv_bfloat16* __restrict__ Whi, const __nv_bfloat16* __restrict__ Wlo,
    const __nv_bfloat16* __restrict__ Xhi, const __nv_bfloat16* __restrict__ Xlo,
    int K, int m0, size_t brow, int k0, int tid)
{
    #pragma unroll
    for (int i = 0; i < 2; ++i) {
        int s = tid + i*256;
        int row = s >> 2, seg = s & 3;
        uint32_t so = row*ROWB + seg*16;
        size_t ga = (size_t)(m0 + row)*K + k0 + seg*8;
        size_t gb = (brow + row)*K + k0 + seg*8;
        cpasync16(sbase +           so, Whi + ga);
        cpasync16(sbase +   TSZ +   so, Wlo + ga);
        cpasync16(sbase + 2*TSZ +   so, Xhi + gb);
        cpasync16(sbase + 3*TSZ +   so, Xlo + gb);
    }
}

template<int EPI>
__global__ __launch_bounds__(256, 2)
void gemm_mma(const __nv_bfloat16* __restrict__ Whi, const __nv_bfloat16* __restrict__ Wlo,
              const __nv_bfloat16* __restrict__ Xhi, const __nv_bfloat16* __restrict__ Xlo,
              const float* __restrict__ bias, const float* __restrict__ mask,
              float* __restrict__ OutF,
              __nv_bfloat16* __restrict__ OutHi, __nv_bfloat16* __restrict__ OutLo,
              int K, int ldo)
{
    extern __shared__ char smem[];
    uint32_t sb = smem_u32(smem);
    int tid = threadIdx.x;
    int b  = blockIdx.z;
    int m0 = blockIdx.y * BM;
    int t0 = blockIdx.x * BN;
    size_t brow = (size_t)b*TT + t0;

    int w = tid >> 5, lane = tid & 31;
    int wm = w & 1, wn = w >> 1;

    float acc[4][4][4];
    #pragma unroll
    for (int i = 0; i < 4; ++i)
        #pragma unroll
        for (int j = 0; j < 4; ++j)
            #pragma unroll
            for (int q = 0; q < 4; ++q) acc[i][j][q] = 0.f;

    uint32_t aoff = (uint32_t)(wm*64 + (lane & 15)) * ROWB + (uint32_t)(lane >> 4) * 16;
    uint32_t boff = (uint32_t)(wn*32 + (lane & 7))  * ROWB + (uint32_t)((lane >> 3) & 1) * 16;

    int nch = K / BK;
    load_stage(sb, Whi, Wlo, Xhi, Xlo, K, m0, brow, 0, tid);
    CP_COMMIT();

    for (int ch = 0; ch < nch; ++ch) {
        if (ch + 1 < nch) {
            load_stage(sb + (uint32_t)((ch + 1) & 1) * STG,
                       Whi, Wlo, Xhi, Xlo, K, m0, brow, (ch + 1) * BK, tid);
            CP_COMMIT();
            CP_WAIT(1);
        } else {
            CP_WAIT(0);
        }
        __syncthreads();

        uint32_t cur = sb + (uint32_t)(ch & 1) * STG;
        uint32_t sAh = cur, sAl = cur + TSZ, sBh = cur + 2*TSZ, sBl = cur + 3*TSZ;
        #pragma unroll
        for (int ks = 0; ks < 2; ++ks) {
            uint32_t Bh[4][2], Bl[4][2];
            #pragma unroll
            for (int ni = 0; ni < 4; ++ni) {
                uint32_t o = boff + (uint32_t)(ni*8)*ROWB + ks*32;
                ldmat2(Bh[ni], sBh + o);
                ldmat2(Bl[ni], sBl + o);
            }
            #pragma unroll
            for (int mi = 0; mi < 4; ++mi) {
                uint32_t Ah[4], Al[4];
                uint32_t o = aoff + (uint32_t)(mi*16)*ROWB + ks*32;
                ldmat4(Ah, sAh + o);
                ldmat4(Al, sAl + o);
                #pragma unroll
                for (int ni = 0; ni < 4; ++ni) {
                    mma_bf16(acc[mi][ni], Ah, Bh[ni]);
                    mma_bf16(acc[mi][ni], Ah, Bl[ni]);
                    mma_bf16(acc[mi][ni], Al, Bh[ni]);
                }
            }
        }
        __syncthreads();   // stage ch fully consumed before refill
    }

    // ---- stage fragments to smem as [t][m] (132-float padded rows) ----
    float* smemf = (float*)smem;
    #pragma unroll
    for (int mi = 0; mi < 4; ++mi) {
        int ma = wm*64 + mi*16 + (lane >> 2);
        #pragma unroll
        for (int ni = 0; ni < 4; ++ni) {
            int tc = wn*32 + ni*8 + (lane & 3)*2;
            float* st = smemf + tc*132;
            st[ma]        = acc[mi][ni][0];
            st[132 + ma]  = acc[mi][ni][1];
            st[ma + 8]    = acc[mi][ni][2];
            st[132 + ma + 8] = acc[mi][ni][3];
        }
    }
    __syncthreads();

    // ---- write phase: coalesced channel-major output -------------------------
    if (EPI == EPI_GLU) {
        int m = lane*4;
        int r0 = m0 + m;
        float b0a = bias[(r0&1)?(HH+(r0>>1)):(r0>>1)];
        float b0g = bias[((r0+1)&1)?(HH+((r0+1)>>1)):((r0+1)>>1)];
        float b1a = bias[((r0+2)&1)?(HH+((r0+2)>>1)):((r0+2)>>1)];
        float b1g = bias[((r0+3)&1)?(HH+((r0+3)>>1)):((r0+3)>>1)];
        #pragma unroll
        for (int p = 0; p < 16; ++p) {
            int r = p*8 + (tid >> 5);
            float4 z = *(float4*)(smemf + r*132 + m);
            float a0 = z.x + b0a, gg0 = z.y + b0g;
            float a1 = z.z + b1a, gg1 = z.w + b1g;
            float2 s;
            s.x = a0 / (1.0f + expf(-gg0));
            s.y = a1 / (1.0f + expf(-gg1));
            *(float2*)(OutF + ((size_t)b*TT + t0 + r)*HH + (m0>>1) + lane*2) = s;
        }
    } else if (EPI == EPI_HILO) {
        int m = lane*4;
        float4 bi = *(const float4*)(bias + m0 + m);
        #pragma unroll
        for (int p = 0; p < 16; ++p) {
            int r = p*8 + (tid >> 5);
            float mv = mask[(size_t)b*TT + t0 + r];
            float4 v = *(float4*)(smemf + r*132 + m);
            v.x = fmaxf(v.x + bi.x, 0.f) * mv;
            v.y = fmaxf(v.y + bi.y, 0.f) * mv;
            v.z = fmaxf(v.z + bi.z, 0.f) * mv;
            v.w = fmaxf(v.w + bi.w, 0.f) * mv;
            __nv_bfloat162 h0 = __floats2bfloat162_rn(v.x, v.y);
            __nv_bfloat162 h1 = __floats2bfloat162_rn(v.z, v.w);
            __nv_bfloat162 l0 = __floats2bfloat162_rn(v.x - __bfloat162float(h0.x),
                                                      v.y - __bfloat162float(h0.y));
            __nv_bfloat162 l1 = __floats2bfloat162_rn(v.z - __bfloat162float(h1.x),
                                                      v.w - __bfloat162float(h1.y));
            size_t o = ((size_t)b*TT + t0 + r)*ldo + m0 + m;
            *(uint2*)(OutHi + o) = make_uint2(bf2u(h0), bf2u(h1));
            *(uint2*)(OutLo + o) = make_uint2(bf2u(l0), bf2u(l1));
        }
    } else {
        int m = lane*4;
        float4 bi = *(const float4*)(bias + m0 + m);
        #pragma unroll
        for (int p = 0; p < 16; ++p) {
            int r = p*8 + (tid >> 5);
            float mv = mask[(size_t)b*TT + t0 + r];
            float4 v = *(float4*)(smemf + r*132 + m);
            v.x = (v.x + bi.x) * mv;
            v.y = (v.y + bi.y) * mv;
            v.z = (v.z + bi.z) * mv;
            v.w = (v.w + bi.w) * mv;
            *(float4*)(OutF + ((size_t)b*TT + t0 + r)*HH + m0 + m) = v;
        }
    }
}

// ---------------- channel LayerNorm (channels contiguous), warp per token ---------
template<int MODE>
__global__ __launch_bounds__(256)
void ln_kernel(const float* __restrict__ res, const float* __restrict__ yy,
               const float* __restrict__ mask,
               const float* __restrict__ gamma, const float* __restrict__ beta,
               float* __restrict__ outF,
               __nv_bfloat16* __restrict__ outHi, __nv_bfloat16* __restrict__ outLo)
{
    int g = blockIdx.x*8 + (threadIdx.x >> 5);
    int lane = threadIdx.x & 31;
    size_t base = (size_t)g*HH;
    float mv = mask[g];

    float4 v[3];
    float s = 0.f, q = 0.f;
    #pragma unroll
    for (int j = 0; j < 3; ++j) {
        float4 r1 = *(const float4*)(res + base + lane*4 + j*128);
        float4 r2 = *(const float4*)(yy  + base + lane*4 + j*128);
        float4 t;
        if (MODE == 0) {
            t.x = fmaf(r1.x, mv, r2.x); t.y = fmaf(r1.y, mv, r2.y);
            t.z = fmaf(r1.z, mv, r2.z); t.w = fmaf(r1.w, mv, r2.w);
        } else {
            t.x = r1.x + r2.x; t.y = r1.y + r2.y;
            t.z = r1.z + r2.z; t.w = r1.w + r2.w;
        }
        v[j] = t;
        s += t.x + t.y + t.z + t.w;
        q += t.x*t.x + t.y*t.y + t.z*t.z + t.w*t.w;
    }
    #pragma unroll
    for (int off = 16; off; off >>= 1) {
        s += __shfl_xor_sync(0xffffffffu, s, off);
        q += __shfl_xor_sync(0xffffffffu, q, off);
    }
    float mu = s * (1.0f/HH);
    float rs = rsqrtf(q * (1.0f/HH) - mu*mu + 1e-4f);

    #pragma unroll
    for (int j = 0; j < 3; ++j) {
        float4 ga = *(const float4*)(gamma + lane*4 + j*128);
        float4 be = *(const float4*)(beta  + lane*4 + j*128);
        float4 t = v[j];
        t.x = (t.x - mu)*rs*ga.x + be.x;
        t.y = (t.y - mu)*rs*ga.y + be.y;
        t.z = (t.z - mu)*rs*ga.z + be.z;
        t.w = (t.w - mu)*rs*ga.w + be.w;
        *(float4*)(outF + base + lane*4 + j*128) = t;
        if (MODE == 0) {
            t.x *= mv; t.y *= mv; t.z *= mv; t.w *= mv;
            __nv_bfloat162 h0 = __floats2bfloat162_rn(t.x, t.y);
            __nv_bfloat162 h1 = __floats2bfloat162_rn(t.z, t.w);
            __nv_bfloat162 l0 = __floats2bfloat162_rn(t.x - __bfloat162float(h0.x),
                                                      t.y - __bfloat162float(h0.y));
            __nv_bfloat162 l1 = __floats2bfloat162_rn(t.z - __bfloat162float(h1.x),
                                                      t.w - __bfloat162float(h1.y));
            *(uint2*)(outHi + base + lane*4 + j*128) = make_uint2(bf2u(h0), bf2u(h1));
            *(uint2*)(outLo + base + lane*4 + j*128) = make_uint2(bf2u(l0), bf2u(l1));
        }
    }
}

// ---------------- host launch -----------------------------------------------------
extern "C" void kernel_launch(void* const* d_in, const int* in_sizes, int n_in,
                              void* d_out, int out_size)
{
    (void)in_sizes; (void)n_in; (void)out_size;
    const float* x      = (const float*)d_in[0];
    const float* mask   = (const float*)d_in[1];
    const float* log_dt = (const float*)d_in[2];
    const float* A_re   = (const float*)d_in[3];
    const float* A_im   = (const float*)d_in[4];
    const float* C_re   = (const float*)d_in[5];
    const float* C_im   = (const float*)d_in[6];
    const float* Dp     = (const float*)d_in[7];
    const float* Wout   = (const float*)d_in[8];
    const float* bout   = (const float*)d_in[9];
    const float* g1     = (const float*)d_in[10];
    const float* be1    = (const float*)d_in[11];
    const float* W1     = (const float*)d_in[12];
    const float* bf1    = (const float*)d_in[13];
    const float* W2     = (const float*)d_in[14];
    const float* bf2    = (const float*)d_in[15];
    const float* g2     = (const float*)d_in[16];
    const float* be2    = (const float*)d_in[17];

    float *ga, *gb, *gc;
    __nv_bfloat16 *xhi, *xlo, *hhi, *hlo, *wouth, *woutl, *w1h, *w1l, *w2h, *w2l;
    cudaGetSymbolAddress((void**)&ga, g_a);
    cudaGetSymbolAddress((void**)&gb, g_b);
    cudaGetSymbolAddress((void**)&gc, g_c);
    cudaGetSymbolAddress((void**)&xhi, g_xhi);
    cudaGetSymbolAddress((void**)&xlo, g_xlo);
    cudaGetSymbolAddress((void**)&hhi, g_hhi);
    cudaGetSymbolAddress((void**)&hlo, g_hlo);
    cudaGetSymbolAddress((void**)&wouth, g_wouth);
    cudaGetSymbolAddress((void**)&woutl, g_woutl);
    cudaGetSymbolAddress((void**)&w1h, g_w1h);
    cudaGetSymbolAddress((void**)&w1l, g_w1l);
    cudaGetSymbolAddress((void**)&w2h, g_w2h);
    cudaGetSymbolAddress((void**)&w2l, g_w2l);

    cudaFuncSetAttribute(gemm_mma<EPI_GLU >, cudaFuncAttributeMaxDynamicSharedMemorySize, GEMM_SMEM);
    cudaFuncSetAttribute(gemm_mma<EPI_HILO>, cudaFuncAttributeMaxDynamicSharedMemorySize, GEMM_SMEM);
    cudaFuncSetAttribute(gemm_mma<EPI_FP32>, cudaFuncAttributeMaxDynamicSharedMemorySize, GEMM_SMEM);

    // weight conversion (all layers, once)
    convw_perm <<<(LYR*2*HH*HH + 255)/256, 256>>>(Wout, wouth, woutl);
    convw_plain<<<(LYR*HF*HH   + 255)/256, 256>>>(W1, w1h, w1l, LYR*HF*HH);
    convw_plain<<<(LYR*HH*HF   + 255)/256, 256>>>(W2, w2h, w2l, LYR*HH*HF);

    // input to [B,T,H]
    transpose_in<<<dim3(TT/32, HH/32, BB), dim3(32, 8)>>>(x, ga);

    for (int l = 0; l < LYR; ++l) {
        scan_kernel<<<(BB*HH)/4, 128>>>(ga, mask, log_dt, A_re, A_im, C_re, C_im, Dp,
                                        xhi, xlo, l);
        gemm_mma<EPI_GLU><<<dim3(TT/BN, (2*HH)/BM, BB), 256, GEMM_SMEM>>>(
            wouth + (size_t)l*2*HH*HH, woutl + (size_t)l*2*HH*HH, xhi, xlo,
            bout + (size_t)l*2*HH, mask, gb, nullptr, nullptr, HH, 0);
        ln_kernel<0><<<NTOK/8, 256>>>(ga, gb, mask, g1 + (size_t)l*HH, be1 + (size_t)l*HH,
                                      gc, xhi, xlo);
        gemm_mma<EPI_HILO><<<dim3(TT/BN, HF/BM, BB), 256, GEMM_SMEM>>>(
            w1h + (size_t)l*HF*HH, w1l + (size_t)l*HF*HH, xhi, xlo,
            bf1 + (size_t)l*HF, mask, nullptr, hhi, hlo, HH, HF);
        gemm_mma<EPI_FP32><<<dim3(TT/BN, HH/BM, BB), 256, GEMM_SMEM>>>(
            w2h + (size_t)l*HH*HF, w2l + (size_t)l*HH*HF, hhi, hlo,
            bf2 + (size_t)l*HH, mask, gb, nullptr, nullptr, HF, 0);
        ln_kernel<1><<<NTOK/8, 256>>>(gc, gb, mask, g2 + (size_t)l*HH, be2 + (size_t)l*HH,
                                      ga, nullptr, nullptr);
    }
    transpose_out<<<dim3(TT/32, HH/32, BB), dim3(32, 8)>>>(ga, mask, (float*)d_out);
}

// round 9
// speedup vs baseline: 2.5047x; 1.0487x over previous
#include <cuda_runtime.h>
#include <cuda_bf16.h>
#include <math.h>
#include <stdint.h>

#define LYR 6
#define BB  16
#define HH  384
#define TT  2048
#define N2  32
#define HF  1536
#define NTOK (BB*TT)

// ---------------- scratch (device globals) ----------------------------------------
__device__ float g_a[(size_t)NTOK*HH];   // xcur [B,T,H] (layer in / LN2 out)
__device__ float g_b[(size_t)NTOK*HH];   // s4 / FFN out
__device__ float g_c[(size_t)NTOK*HH];   // x1 (LN1 out)
__device__ __nv_bfloat16 g_xhi[(size_t)NTOK*HH], g_xlo[(size_t)NTOK*HH]; // K=384 operand
__device__ __nv_bfloat16 g_hhi[(size_t)NTOK*HF], g_hlo[(size_t)NTOK*HF]; // K=1536 operand
__device__ __nv_bfloat16 g_wouth[LYR*2*HH*HH], g_woutl[LYR*2*HH*HH];     // GLU-permuted
__device__ __nv_bfloat16 g_w1h[LYR*HF*HH],  g_w1l[LYR*HF*HH];
__device__ __nv_bfloat16 g_w2h[LYR*HH*HF],  g_w2l[LYR*HH*HF];

// ================= helpers =================
__device__ __forceinline__ uint32_t smem_u32(const void* p) {
    uint32_t a;
    asm("{ .reg .u64 t; cvta.to.shared.u64 t, %1; cvt.u32.u64 %0, t; }" : "=r"(a) : "l"(p));
    return a;
}
__device__ __forceinline__ void cpasync16(uint32_t saddr, const void* g) {
    asm volatile("cp.async.cg.shared.global [%0], [%1], 16;" :: "r"(saddr), "l"(g));
}
#define CP_COMMIT() asm volatile("cp.async.commit_group;" ::: "memory")
#define CP_WAIT(n)  asm volatile("cp.async.wait_group %0;" :: "n"(n) : "memory")

__device__ __forceinline__ void ldmat4(uint32_t* r, uint32_t a) {
    asm volatile("ldmatrix.sync.aligned.m8n8.x4.shared.b16 {%0,%1,%2,%3}, [%4];"
        : "=r"(r[0]), "=r"(r[1]), "=r"(r[2]), "=r"(r[3]) : "r"(a));
}
__device__ __forceinline__ void ldmat2(uint32_t* r, uint32_t a) {
    asm volatile("ldmatrix.sync.aligned.m8n8.x2.shared.b16 {%0,%1}, [%2];"
        : "=r"(r[0]), "=r"(r[1]) : "r"(a));
}
__device__ __forceinline__ void mma_bf16(float* d, const uint32_t* a, const uint32_t* b) {
    asm volatile("mma.sync.aligned.m16n8k16.row.col.f32.bf16.bf16.f32 "
        "{%0,%1,%2,%3}, {%4,%5,%6,%7}, {%8,%9}, {%0,%1,%2,%3};"
        : "+f"(d[0]), "+f"(d[1]), "+f"(d[2]), "+f"(d[3])
        : "r"(a[0]), "r"(a[1]), "r"(a[2]), "r"(a[3]), "r"(b[0]), "r"(b[1]));
}
__device__ __forceinline__ uint32_t bf2u(__nv_bfloat162 v) {
    return *reinterpret_cast<uint32_t*>(&v);
}

// ---------------- weight conversion (once per call, all layers) --------------------
__global__ void convw_plain(const float* __restrict__ W,
                            __nv_bfloat16* __restrict__ hi, __nv_bfloat16* __restrict__ lo,
                            int n)
{
    int i = blockIdx.x * blockDim.x + threadIdx.x;
    if (i >= n) return;
    float w = W[i];
    __nv_bfloat16 h = __float2bfloat16(w);
    hi[i] = h;
    lo[i] = __float2bfloat16(w - __bfloat162float(h));
}

// Wout with GLU row permutation: dest row r -> src row (r&1) ? HH + r/2 : r/2
__global__ void convw_perm(const float* __restrict__ W,
                           __nv_bfloat16* __restrict__ hi, __nv_bfloat16* __restrict__ lo)
{
    int i = blockIdx.x * blockDim.x + threadIdx.x;
    if (i >= LYR*2*HH*HH) return;
    int k = i % HH;
    int rr = i / HH;
    int r = rr % (2*HH);
    int l = rr / (2*HH);
    int src = (r & 1) ? (HH + (r >> 1)) : (r >> 1);
    float w = W[((size_t)l*2*HH + src)*HH + k];
    __nv_bfloat16 h = __float2bfloat16(w);
    hi[i] = h;
    lo[i] = __float2bfloat16(w - __bfloat162float(h));
}

// ---------------- transposes ------------------------------------------------------
__global__ void transpose_in(const float* __restrict__ in, float* __restrict__ out)
{
    __shared__ float tile[32][33];
    int b = blockIdx.z, t0 = blockIdx.x*32, h0 = blockIdx.y*32;
    int tx = threadIdx.x, ty = threadIdx.y;
    #pragma unroll
    for (int i = 0; i < 4; ++i)
        tile[ty + i*8][tx] = in[((size_t)b*HH + h0 + ty + i*8)*TT + t0 + tx];
    __syncthreads();
    #pragma unroll
    for (int i = 0; i < 4; ++i)
        out[((size_t)b*TT + t0 + ty + i*8)*HH + h0 + tx] = tile[tx][ty + i*8];
}
__global__ void transpose_out(const float* __restrict__ in, const float* __restrict__ mask,
                              float* __restrict__ out)
{
    __shared__ float tile[32][33];
    int b = blockIdx.z, t0 = blockIdx.x*32, h0 = blockIdx.y*32;
    int tx = threadIdx.x, ty = threadIdx.y;
    #pragma unroll
    for (int i = 0; i < 4; ++i)
        tile[ty + i*8][tx] = in[((size_t)b*TT + t0 + ty + i*8)*HH + h0 + tx];
    __syncthreads();
    float mv = mask[(size_t)b*TT + t0 + tx];
    #pragma unroll
    for (int i = 0; i < 4; ++i)
        out[((size_t)b*HH + h0 + ty + i*8)*TT + t0 + tx] = tile[tx][ty + i*8] * mv;
}

// ---------------- S4D scan (smem-transpose reduce), writes bf16 hi/lo [B,T,H] -----
__global__ __launch_bounds__(128)
void scan_kernel(const float* __restrict__ x, const float* __restrict__ mask,
                 const float* __restrict__ log_dt,
                 const float* __restrict__ A_re, const float* __restrict__ A_im,
                 const float* __restrict__ C_re, const float* __restrict__ C_im,
                 const float* __restrict__ Dp,
                 __nv_bfloat16* __restrict__ yhi, __nv_bfloat16* __restrict__ ylo, int layer)
{
    __shared__ float sx[4][33];
    __shared__ float sc[4][32][33];
    int w = threadIdx.x >> 5, lane = threadIdx.x & 31;
    int wid = blockIdx.x*4 + w;
    int b = wid / HH, h = wid % HH;

    float dt = expf(log_dt[layer*HH + h]);
    int pidx = (layer*HH + h) * N2 + lane;
    float ar = A_re[pidx], ai = A_im[pidx];
    float dre = ar * dt, dim = ai * dt;
    float e   = expf(dre);
    float wre = e * cosf(dim);
    float wim = e * sinf(dim);
    float nre = wre - 1.0f, nim = wim;
    float d2  = ar*ar + ai*ai;
    float qre = (nre*ar + nim*ai) / d2;
    float qim = (nim*ar - nre*ai) / d2;
    float cre = C_re[pidx], cim = C_im[pidx];
    float cdre = cre*qre - cim*qim;
    float cdim = cre*qim + cim*qre;
    float Dv = Dp[layer*HH + h];

    const float* mr = mask + (size_t)b * TT;
    float sre = 0.f, sim = 0.f;

    for (int c = 0; c < TT/32; ++c) {
        int t0 = c*32;
        float xv = x[((size_t)b*TT + t0 + lane)*HH + h] * mr[t0 + lane];
        sx[w][lane] = xv;
        __syncwarp();
        const float* sxr = sx[w];
        #pragma unroll
        for (int j = 0; j < 32; ++j) {
            float xj = sxr[j];
            float tre = fmaf(wre, sre, fmaf(-wim, sim, xj));
            float tim = fmaf(wre, sim, wim * sre);
            sre = tre; sim = tim;
            sc[w][lane][j] = fmaf(cdre, sre, -cdim * sim);
        }
        __syncwarp();
        float sum = 0.f;
        #pragma unroll
        for (int n = 0; n < 32; ++n) sum += sc[w][n][lane];
        float yv = 2.0f*sum + Dv * sxr[lane];
        yv = 0.5f * yv * (1.0f + erff(yv * 0.70710678118654752f));
        __nv_bfloat16 hv = __float2bfloat16(yv);
        size_t o = ((size_t)b*TT + t0 + lane)*HH + h;
        yhi[o] = hv;
        ylo[o] = __float2bfloat16(yv - __bfloat162float(hv));
        __syncwarp();
    }
}

// ---------------- split-bf16 mma.sync GEMM, packed 128B rows + XOR swizzle ---------
// smem tile row m (128B) = [ hi(32 bf16) | lo(32 bf16) ], chunk c at (c ^ (m&7))*16
#define BM 128
#define BN 128
#define BK 32
#define ATILE 16384                 // 128 rows * 128B
#define STAGE (2*ATILE)             // A + B = 32KB
#define NSTAGE 3
#define GEMM_SMEM (NSTAGE*STAGE)    // 98304; epilogue needs 128*132*4 = 67584

#define EPI_GLU  0
#define EPI_HILO 1
#define EPI_FP32 2

__device__ __forceinline__ void load_stage(
    uint32_t sbase,
    const __nv_bfloat16* __restrict__ Whi, const __nv_bfloat16* __restrict__ Wlo,
    const __nv_bfloat16* __restrict__ Xhi, const __nv_bfloat16* __restrict__ Xlo,
    int K, int m0, size_t brow, int k0, int tid)
{
    #pragma unroll
    for (int i = 0; i < 4; ++i) {
        int s = tid + i*256;
        int row = s >> 3, c = s & 7;
        uint32_t dst = sbase + (uint32_t)row*128 + (uint32_t)((c ^ (row & 7)) << 4);
        const __nv_bfloat16* srca = (c < 4)
            ? (Whi + (size_t)(m0 + row)*K + k0 + c*8)
            : (Wlo + (size_t)(m0 + row)*K + k0 + (c - 4)*8);
        cpasync16(dst, srca);
        const __nv_bfloat16* srcb = (c < 4)
            ? (Xhi + (brow + row)*K + k0 + c*8)
            : (Xlo + (brow + row)*K + k0 + (c - 4)*8);
        cpasync16(dst + ATILE, srcb);
    }
}

template<int EPI>
__global__ __launch_bounds__(256, 2)
void gemm_mma(const __nv_bfloat16* __restrict__ Whi, const __nv_bfloat16* __restrict__ Wlo,
              const __nv_bfloat16* __restrict__ Xhi, const __nv_bfloat16* __restrict__ Xlo,
              const float* __restrict__ bias, const float* __restrict__ mask,
              float* __restrict__ OutF,
              __nv_bfloat16* __restrict__ OutHi, __nv_bfloat16* __restrict__ OutLo,
              int K, int ldo)
{
    extern __shared__ char smem[];
    uint32_t sb = smem_u32(smem);
    int tid = threadIdx.x;
    int b  = blockIdx.z;
    int m0 = blockIdx.y * BM;
    int t0 = blockIdx.x * BN;
    size_t brow = (size_t)b*TT + t0;

    int w = tid >> 5, lane = tid & 31;
    int wm = w & 1, wn = w >> 1;

    float acc[4][4][4];
    #pragma unroll
    for (int i = 0; i < 4; ++i)
        #pragma unroll
        for (int j = 0; j < 4; ++j)
            #pragma unroll
            for (int q = 0; q < 4; ++q) acc[i][j][q] = 0.f;

    // per-lane ldmatrix row bases (row&7 invariant under mi*16 / ni*8 shifts)
    int arow  = wm*64 + (lane & 15);
    int amask = arow & 7;
    int ahalf = lane >> 4;            // k-half select for A
    int brw   = wn*32 + (lane & 7);
    int bmask = brw & 7;
    int bhalf = (lane >> 3) & 1;      // k-half select for B

    int nch = K / BK;
    load_stage(sb,          Whi, Wlo, Xhi, Xlo, K, m0, brow, 0,  tid);
    CP_COMMIT();
    load_stage(sb + STAGE,  Whi, Wlo, Xhi, Xlo, K, m0, brow, BK, tid);
    CP_COMMIT();

    for (int ch = 0; ch < nch; ++ch) {
        CP_WAIT(1);
        __syncthreads();

        if (ch + 2 < nch)
            load_stage(sb + (uint32_t)((ch + 2) % NSTAGE) * STAGE,
                       Whi, Wlo, Xhi, Xlo, K, m0, brow, (ch + 2) * BK, tid);
        CP_COMMIT();

        uint32_t cur = sb + (uint32_t)(ch % NSTAGE) * STAGE;
        uint32_t sA = cur, sB = cur + ATILE;
        uint32_t aBase = sA + (uint32_t)arow * 128;
        uint32_t bBase = sB + (uint32_t)brw  * 128;

        #pragma unroll
        for (int ks = 0; ks < 2; ++ks) {
            uint32_t axH = (uint32_t)(((ks*2 + ahalf)     ^ amask) << 4);
            uint32_t axL = (uint32_t)(((ks*2 + ahalf + 4) ^ amask) << 4);
            uint32_t bxH = (uint32_t)(((ks*2 + bhalf)     ^ bmask) << 4);
            uint32_t bxL = (uint32_t)(((ks*2 + bhalf + 4) ^ bmask) << 4);

            uint32_t Bh[4][2], Bl[4][2];
            #pragma unroll
            for (int ni = 0; ni < 4; ++ni) {
                uint32_t base = bBase + (uint32_t)(ni*8)*128;
                ldmat2(Bh[ni], base + bxH);
                ldmat2(Bl[ni], base + bxL);
            }
            #pragma unroll
            for (int mi = 0; mi < 4; ++mi) {
                uint32_t base = aBase + (uint32_t)(mi*16)*128;
                uint32_t Ah[4], Al[4];
                ldmat4(Ah, base + axH);
                ldmat4(Al, base + axL);
                #pragma unroll
                for (int ni = 0; ni < 4; ++ni) {
                    mma_bf16(acc[mi][ni], Ah, Bh[ni]);
                    mma_bf16(acc[mi][ni], Ah, Bl[ni]);
                    mma_bf16(acc[mi][ni], Al, Bh[ni]);
                }
            }
        }
    }
    __syncthreads();   // all warps done with mainloop before smem reuse

    // ---- stage fragments to smem as [t][m] (132-float padded rows) ----
    float* smemf = (float*)smem;
    #pragma unroll
    for (int mi = 0; mi < 4; ++mi) {
        int ma = wm*64 + mi*16 + (lane >> 2);
        #pragma unroll
        for (int ni = 0; ni < 4; ++ni) {
            int tc = wn*32 + ni*8 + (lane & 3)*2;
            float* st = smemf + tc*132;
            st[ma]        = acc[mi][ni][0];
            st[132 + ma]  = acc[mi][ni][1];
            st[ma + 8]    = acc[mi][ni][2];
            st[132 + ma + 8] = acc[mi][ni][3];
        }
    }
    __syncthreads();

    // ---- write phase: coalesced channel-major output -------------------------
    if (EPI == EPI_GLU) {
        int m = lane*4;
        int r0 = m0 + m;
        float b0a = bias[(r0&1)?(HH+(r0>>1)):(r0>>1)];
        float b0g = bias[((r0+1)&1)?(HH+((r0+1)>>1)):((r0+1)>>1)];
        float b1a = bias[((r0+2)&1)?(HH+((r0+2)>>1)):((r0+2)>>1)];
        float b1g = bias[((r0+3)&1)?(HH+((r0+3)>>1)):((r0+3)>>1)];
        #pragma unroll
        for (int p = 0; p < 16; ++p) {
            int r = p*8 + (tid >> 5);
            float4 z = *(float4*)(smemf + r*132 + m);
            float a0 = z.x + b0a, gg0 = z.y + b0g;
            float a1 = z.z + b1a, gg1 = z.w + b1g;
            float2 s;
            s.x = a0 / (1.0f + expf(-gg0));
            s.y = a1 / (1.0f + expf(-gg1));
            *(float2*)(OutF + ((size_t)b*TT + t0 + r)*HH + (m0>>1) + lane*2) = s;
        }
    } else if (EPI == EPI_HILO) {
        int m = lane*4;
        float4 bi = *(const float4*)(bias + m0 + m);
        #pragma unroll
        for (int p = 0; p < 16; ++p) {
            int r = p*8 + (tid >> 5);
            float mv = mask[(size_t)b*TT + t0 + r];
            float4 v = *(float4*)(smemf + r*132 + m);
            v.x = fmaxf(v.x + bi.x, 0.f) * mv;
            v.y = fmaxf(v.y + bi.y, 0.f) * mv;
            v.z = fmaxf(v.z + bi.z, 0.f) * mv;
            v.w = fmaxf(v.w + bi.w, 0.f) * mv;
            __nv_bfloat162 h0 = __floats2bfloat162_rn(v.x, v.y);
            __nv_bfloat162 h1 = __floats2bfloat162_rn(v.z, v.w);
            __nv_bfloat162 l0 = __floats2bfloat162_rn(v.x - __bfloat162float(h0.x),
                                                      v.y - __bfloat162float(h0.y));
            __nv_bfloat162 l1 = __floats2bfloat162_rn(v.z - __bfloat162float(h1.x),
                                                      v.w - __bfloat162float(h1.y));
            size_t o = ((size_t)b*TT + t0 + r)*ldo + m0 + m;
            *(uint2*)(OutHi + o) = make_uint2(bf2u(h0), bf2u(h1));
            *(uint2*)(OutLo + o) = make_uint2(bf2u(l0), bf2u(l1));
        }
    } else {
        int m = lane*4;
        float4 bi = *(const float4*)(bias + m0 + m);
        #pragma unroll
        for (int p = 0; p < 16; ++p) {
            int r = p*8 + (tid >> 5);
            float mv = mask[(size_t)b*TT + t0 + r];
            float4 v = *(float4*)(smemf + r*132 + m);
            v.x = (v.x + bi.x) * mv;
            v.y = (v.y + bi.y) * mv;
            v.z = (v.z + bi.z) * mv;
            v.w = (v.w + bi.w) * mv;
            *(float4*)(OutF + ((size_t)b*TT + t0 + r)*HH + m0 + m) = v;
        }
    }
}

// ---------------- channel LayerNorm (channels contiguous), warp per token ---------
template<int MODE>
__global__ __launch_bounds__(256)
void ln_kernel(const float* __restrict__ res, const float* __restrict__ yy,
               const float* __restrict__ mask,
               const float* __restrict__ gamma, const float* __restrict__ beta,
               float* __restrict__ outF,
               __nv_bfloat16* __restrict__ outHi, __nv_bfloat16* __restrict__ outLo)
{
    int g = blockIdx.x*8 + (threadIdx.x >> 5);
    int lane = threadIdx.x & 31;
    size_t base = (size_t)g*HH;
    float mv = mask[g];

    float4 v[3];
    float s = 0.f, q = 0.f;
    #pragma unroll
    for (int j = 0; j < 3; ++j) {
        float4 r1 = *(const float4*)(res + base + lane*4 + j*128);
        float4 r2 = *(const float4*)(yy  + base + lane*4 + j*128);
        float4 t;
        if (MODE == 0) {
            t.x = fmaf(r1.x, mv, r2.x); t.y = fmaf(r1.y, mv, r2.y);
            t.z = fmaf(r1.z, mv, r2.z); t.w = fmaf(r1.w, mv, r2.w);
        } else {
            t.x = r1.x + r2.x; t.y = r1.y + r2.y;
            t.z = r1.z + r2.z; t.w = r1.w + r2.w;
        }
        v[j] = t;
        s += t.x + t.y + t.z + t.w;
        q += t.x*t.x + t.y*t.y + t.z*t.z + t.w*t.w;
    }
    #pragma unroll
    for (int off = 16; off; off >>= 1) {
        s += __shfl_xor_sync(0xffffffffu, s, off);
        q += __shfl_xor_sync(0xffffffffu, q, off);
    }
    float mu = s * (1.0f/HH);
    float rs = rsqrtf(q * (1.0f/HH) - mu*mu + 1e-4f);

    #pragma unroll
    for (int j = 0; j < 3; ++j) {
        float4 ga = *(const float4*)(gamma + lane*4 + j*128);
        float4 be = *(const float4*)(beta  + lane*4 + j*128);
        float4 t = v[j];
        t.x = (t.x - mu)*rs*ga.x + be.x;
        t.y = (t.y - mu)*rs*ga.y + be.y;
        t.z = (t.z - mu)*rs*ga.z + be.z;
        t.w = (t.w - mu)*rs*ga.w + be.w;
        *(float4*)(outF + base + lane*4 + j*128) = t;
        if (MODE == 0) {
            t.x *= mv; t.y *= mv; t.z *= mv; t.w *= mv;
            __nv_bfloat162 h0 = __floats2bfloat162_rn(t.x, t.y);
            __nv_bfloat162 h1 = __floats2bfloat162_rn(t.z, t.w);
            __nv_bfloat162 l0 = __floats2bfloat162_rn(t.x - __bfloat162float(h0.x),
                                                      t.y - __bfloat162float(h0.y));
            __nv_bfloat162 l1 = __floats2bfloat162_rn(t.z - __bfloat162float(h1.x),
                                                      t.w - __bfloat162float(h1.y));
            *(uint2*)(outHi + base + lane*4 + j*128) = make_uint2(bf2u(h0), bf2u(h1));
            *(uint2*)(outLo + base + lane*4 + j*128) = make_uint2(bf2u(l0), bf2u(l1));
        }
    }
}

// ---------------- host launch -----------------------------------------------------
extern "C" void kernel_launch(void* const* d_in, const int* in_sizes, int n_in,
                              void* d_out, int out_size)
{
    (void)in_sizes; (void)n_in; (void)out_size;
    const float* x      = (const float*)d_in[0];
    const float* mask   = (const float*)d_in[1];
    const float* log_dt = (const float*)d_in[2];
    const float* A_re   = (const float*)d_in[3];
    const float* A_im   = (const float*)d_in[4];
    const float* C_re   = (const float*)d_in[5];
    const float* C_im   = (const float*)d_in[6];
    const float* Dp     = (const float*)d_in[7];
    const float* Wout   = (const float*)d_in[8];
    const float* bout   = (const float*)d_in[9];
    const float* g1     = (const float*)d_in[10];
    const float* be1    = (const float*)d_in[11];
    const float* W1     = (const float*)d_in[12];
    const float* bf1    = (const float*)d_in[13];
    const float* W2     = (const float*)d_in[14];
    const float* bf2    = (const float*)d_in[15];
    const float* g2     = (const float*)d_in[16];
    const float* be2    = (const float*)d_in[17];

    float *ga, *gb, *gc;
    __nv_bfloat16 *xhi, *xlo, *hhi, *hlo, *wouth, *woutl, *w1h, *w1l, *w2h, *w2l;
    cudaGetSymbolAddress((void**)&ga, g_a);
    cudaGetSymbolAddress((void**)&gb, g_b);
    cudaGetSymbolAddress((void**)&gc, g_c);
    cudaGetSymbolAddress((void**)&xhi, g_xhi);
    cudaGetSymbolAddress((void**)&xlo, g_xlo);
    cudaGetSymbolAddress((void**)&hhi, g_hhi);
    cudaGetSymbolAddress((void**)&hlo, g_hlo);
    cudaGetSymbolAddress((void**)&wouth, g_wouth);
    cudaGetSymbolAddress((void**)&woutl, g_woutl);
    cudaGetSymbolAddress((void**)&w1h, g_w1h);
    cudaGetSymbolAddress((void**)&w1l, g_w1l);
    cudaGetSymbolAddress((void**)&w2h, g_w2h);
    cudaGetSymbolAddress((void**)&w2l, g_w2l);

    cudaFuncSetAttribute(gemm_mma<EPI_GLU >, cudaFuncAttributeMaxDynamicSharedMemorySize, GEMM_SMEM);
    cudaFuncSetAttribute(gemm_mma<EPI_HILO>, cudaFuncAttributeMaxDynamicSharedMemorySize, GEMM_SMEM);
    cudaFuncSetAttribute(gemm_mma<EPI_FP32>, cudaFuncAttributeMaxDynamicSharedMemorySize, GEMM_SMEM);

    // weight conversion (all layers, once)
    convw_perm <<<(LYR*2*HH*HH + 255)/256, 256>>>(Wout, wouth, woutl);
    convw_plain<<<(LYR*HF*HH   + 255)/256, 256>>>(W1, w1h, w1l, LYR*HF*HH);
    convw_plain<<<(LYR*HH*HF   + 255)/256, 256>>>(W2, w2h, w2l, LYR*HH*HF);

    // input to [B,T,H]
    transpose_in<<<dim3(TT/32, HH/32, BB), dim3(32, 8)>>>(x, ga);

    for (int l = 0; l < LYR; ++l) {
        scan_kernel<<<(BB*HH)/4, 128>>>(ga, mask, log_dt, A_re, A_im, C_re, C_im, Dp,
                                        xhi, xlo, l);
        gemm_mma<EPI_GLU><<<dim3(TT/BN, (2*HH)/BM, BB), 256, GEMM_SMEM>>>(
            wouth + (size_t)l*2*HH*HH, woutl + (size_t)l*2*HH*HH, xhi, xlo,
            bout + (size_t)l*2*HH, mask, gb, nullptr, nullptr, HH, 0);
        ln_kernel<0><<<NTOK/8, 256>>>(ga, gb, mask, g1 + (size_t)l*HH, be1 + (size_t)l*HH,
                                      gc, xhi, xlo);
        gemm_mma<EPI_HILO><<<dim3(TT/BN, HF/BM, BB), 256, GEMM_SMEM>>>(
            w1h + (size_t)l*HF*HH, w1l + (size_t)l*HF*HH, xhi, xlo,
            bf1 + (size_t)l*HF, mask, nullptr, hhi, hlo, HH, HF);
        gemm_mma<EPI_FP32><<<dim3(TT/BN, HH/BM, BB), 256, GEMM_SMEM>>>(
            w2h + (size_t)l*HH*HF, w2l + (size_t)l*HH*HF, hhi, hlo,
            bf2 + (size_t)l*HH, mask, gb, nullptr, nullptr, HF, 0);
        ln_kernel<1><<<NTOK/8, 256>>>(gc, gb, mask, g2 + (size_t)l*HH, be2 + (size_t)l*HH,
                                      ga, nullptr, nullptr);
    }
    transpose_out<<<dim3(TT/32, HH/32, BB), dim3(32, 8)>>>(ga, mask, (float*)d_out);
}

// round 11
// speedup vs baseline: 3.4402x; 1.3735x over previous
#include <cuda_runtime.h>
#include <cuda_bf16.h>
#include <math.h>
#include <stdint.h>

#define LYR 6
#define BB  16
#define HH  384
#define TT  2048
#define N2  32
#define HF  1536
#define NTOK (BB*TT)

// ---------------- scratch (device globals) ----------------------------------------
__device__ float g_a[(size_t)NTOK*HH];   // xcur [B,T,H]
__device__ float g_b[(size_t)NTOK*HH];   // s4 / FFN out
__device__ float g_c[(size_t)NTOK*HH];   // x1 (LN1 out)
__device__ float g_xt[(size_t)NTOK*HH];  // tf32-rounded K=384 operand [B,T,H]
__device__ float g_ht[(size_t)NTOK*HF];  // tf32-rounded K=1536 operand [B,T,HF]
__device__ float g_woutt[LYR*2*HH*HH];   // GLU-permuted tf32 weights
__device__ float g_w1t[LYR*HF*HH];
__device__ float g_w2t[LYR*HH*HF];

// ================= helpers =================
__device__ __forceinline__ uint32_t smem_u32(const void* p) {
    uint32_t a;
    asm("{ .reg .u64 t; cvta.to.shared.u64 t, %1; cvt.u32.u64 %0, t; }" : "=r"(a) : "l"(p));
    return a;
}
__device__ __forceinline__ void cpasync16(uint32_t saddr, const void* g) {
    asm volatile("cp.async.cg.shared.global [%0], [%1], 16;" :: "r"(saddr), "l"(g));
}
#define CP_COMMIT() asm volatile("cp.async.commit_group;" ::: "memory")
#define CP_WAIT(n)  asm volatile("cp.async.wait_group %0;" :: "n"(n) : "memory")

__device__ __forceinline__ uint32_t tf32r(float x) {
    uint32_t u;
    asm("cvt.rna.tf32.f32 %0, %1;" : "=r"(u) : "f"(x));
    return u;
}
__device__ __forceinline__ float tf32rf(float x) { return __uint_as_float(tf32r(x)); }

__device__ __forceinline__ void mma_tf32(float* d, uint32_t a0, uint32_t a1,
                                         uint32_t a2, uint32_t a3,
                                         uint32_t b0, uint32_t b1) {
    asm volatile("mma.sync.aligned.m16n8k8.row.col.f32.tf32.tf32.f32 "
        "{%0,%1,%2,%3}, {%4,%5,%6,%7}, {%8,%9}, {%0,%1,%2,%3};"
        : "+f"(d[0]), "+f"(d[1]), "+f"(d[2]), "+f"(d[3])
        : "r"(a0), "r"(a1), "r"(a2), "r"(a3), "r"(b0), "r"(b1));
}

// ---------------- weight conversion: round to tf32 once, all layers ---------------
__global__ void convw_plain(const float* __restrict__ W, float* __restrict__ o, int n)
{
    int i = blockIdx.x * blockDim.x + threadIdx.x;
    if (i >= n) return;
    o[i] = tf32rf(W[i]);
}
// Wout with GLU row permutation: dest row r -> src row (r&1) ? HH + r/2 : r/2
__global__ void convw_perm(const float* __restrict__ W, float* __restrict__ o)
{
    int i = blockIdx.x * blockDim.x + threadIdx.x;
    if (i >= LYR*2*HH*HH) return;
    int k = i % HH;
    int rr = i / HH;
    int r = rr % (2*HH);
    int l = rr / (2*HH);
    int src = (r & 1) ? (HH + (r >> 1)) : (r >> 1);
    o[i] = tf32rf(W[((size_t)l*2*HH + src)*HH + k]);
}

// ---------------- transposes ------------------------------------------------------
__global__ void transpose_in(const float* __restrict__ in, float* __restrict__ out)
{
    __shared__ float tile[32][33];
    int b = blockIdx.z, t0 = blockIdx.x*32, h0 = blockIdx.y*32;
    int tx = threadIdx.x, ty = threadIdx.y;
    #pragma unroll
    for (int i = 0; i < 4; ++i)
        tile[ty + i*8][tx] = in[((size_t)b*HH + h0 + ty + i*8)*TT + t0 + tx];
    __syncthreads();
    #pragma unroll
    for (int i = 0; i < 4; ++i)
        out[((size_t)b*TT + t0 + ty + i*8)*HH + h0 + tx] = tile[tx][ty + i*8];
}
__global__ void transpose_out(const float* __restrict__ in, const float* __restrict__ mask,
                              float* __restrict__ out)
{
    __shared__ float tile[32][33];
    int b = blockIdx.z, t0 = blockIdx.x*32, h0 = blockIdx.y*32;
    int tx = threadIdx.x, ty = threadIdx.y;
    #pragma unroll
    for (int i = 0; i < 4; ++i)
        tile[ty + i*8][tx] = in[((size_t)b*TT + t0 + ty + i*8)*HH + h0 + tx];
    __syncthreads();
    float mv = mask[(size_t)b*TT + t0 + tx];
    #pragma unroll
    for (int i = 0; i < 4; ++i)
        out[((size_t)b*HH + h0 + ty + i*8)*TT + t0 + tx] = tile[tx][ty + i*8] * mv;
}

// ---------------- S4D scan -> tf32-rounded fp32 [B,T,H] ---------------------------
__global__ __launch_bounds__(128)
void scan_kernel(const float* __restrict__ x, const float* __restrict__ mask,
                 const float* __restrict__ log_dt,
                 const float* __restrict__ A_re, const float* __restrict__ A_im,
                 const float* __restrict__ C_re, const float* __restrict__ C_im,
                 const float* __restrict__ Dp,
                 float* __restrict__ yt, int layer)
{
    __shared__ float sx[4][33];
    __shared__ float sc[4][32][33];
    int w = threadIdx.x >> 5, lane = threadIdx.x & 31;
    int wid = blockIdx.x*4 + w;
    int b = wid / HH, h = wid % HH;

    float dt = expf(log_dt[layer*HH + h]);
    int pidx = (layer*HH + h) * N2 + lane;
    float ar = A_re[pidx], ai = A_im[pidx];
    float dre = ar * dt, dim = ai * dt;
    float e   = expf(dre);
    float wre = e * cosf(dim);
    float wim = e * sinf(dim);
    float nre = wre - 1.0f, nim = wim;
    float d2  = ar*ar + ai*ai;
    float qre = (nre*ar + nim*ai) / d2;
    float qim = (nim*ar - nre*ai) / d2;
    float cre = C_re[pidx], cim = C_im[pidx];
    float cdre = cre*qre - cim*qim;
    float cdim = cre*qim + cim*qre;
    float Dv = Dp[layer*HH + h];

    const float* mr = mask + (size_t)b * TT;
    float sre = 0.f, sim = 0.f;

    for (int c = 0; c < TT/32; ++c) {
        int t0 = c*32;
        float xv = x[((size_t)b*TT + t0 + lane)*HH + h] * mr[t0 + lane];
        sx[w][lane] = xv;
        __syncwarp();
        const float* sxr = sx[w];
        #pragma unroll
        for (int j = 0; j < 32; ++j) {
            float xj = sxr[j];
            float tre = fmaf(wre, sre, fmaf(-wim, sim, xj));
            float tim = fmaf(wre, sim, wim * sre);
            sre = tre; sim = tim;
            sc[w][lane][j] = fmaf(cdre, sre, -cdim * sim);
        }
        __syncwarp();
        float sum = 0.f;
        #pragma unroll
        for (int n = 0; n < 32; ++n) sum += sc[w][n][lane];
        float yv = 2.0f*sum + Dv * sxr[lane];
        yv = 0.5f * yv * (1.0f + erff(yv * 0.70710678118654752f));
        yt[((size_t)b*TT + t0 + lane)*HH + h] = tf32rf(yv);
        __syncwarp();
    }
}

// ---------------- single-pass tf32 mma.sync GEMM ----------------------------------
// smem tile row m (128B) = 32 fp32 k-values; 16B chunk c stored at (c ^ (m&7))*16
#define BM 128
#define BN 128
#define BK 32
#define ATILE 16384                 // 128 rows * 128B
#define STAGE (2*ATILE)             // A + B = 32KB
#define NSTAGE 3
#define GEMM_SMEM (NSTAGE*STAGE)    // 98304; epilogue needs 128*132*4 = 67584

#define EPI_GLU  0
#define EPI_TF   1
#define EPI_FP32 2

__device__ __forceinline__ void load_stage(
    uint32_t sbase,
    const float* __restrict__ Wt, const float* __restrict__ Xt,
    int K, int m0, size_t brow, int k0, int tid)
{
    #pragma unroll
    for (int i = 0; i < 4; ++i) {
        int s = tid + i*256;
        int row = s >> 3, c = s & 7;
        uint32_t dst = sbase + (uint32_t)row*128 + (uint32_t)((c ^ (row & 7)) << 4);
        cpasync16(dst,         Wt + (size_t)(m0 + row)*K + k0 + c*4);
        cpasync16(dst + ATILE, Xt + (brow + row)*K + k0 + c*4);
    }
}

template<int EPI>
__global__ __launch_bounds__(256, 2)
void gemm_mma(const float* __restrict__ Wt, const float* __restrict__ Xt,
              const float* __restrict__ bias, const float* __restrict__ mask,
              float* __restrict__ OutF, float* __restrict__ OutT,
              int K, int ldo)
{
    extern __shared__ char smem[];
    uint32_t sb = smem_u32(smem);
    int tid = threadIdx.x;
    int b  = blockIdx.z;
    int m0 = blockIdx.y * BM;
    int t0 = blockIdx.x * BN;
    size_t brow = (size_t)b*TT + t0;

    int w = tid >> 5, lane = tid & 31;
    int wm = w & 1, wn = w >> 1;

    float acc[4][4][4];
    #pragma unroll
    for (int i = 0; i < 4; ++i)
        #pragma unroll
        for (int j = 0; j < 4; ++j)
            #pragma unroll
            for (int q = 0; q < 4; ++q) acc[i][j][q] = 0.f;

    // fragment addressing: row-within-8 == lane>>2 for every A row / B n-row
    uint32_t xm  = (uint32_t)(lane >> 2);       // XOR mask (row & 7)
    uint32_t off = (uint32_t)(lane & 3) * 4;    // float within 16B chunk
    uint32_t aRow0 = (uint32_t)(wm*64 + (lane >> 2)) * 128 + off;
    uint32_t bRow0 = (uint32_t)(wn*32 + (lane >> 2)) * 128 + off;

    int nch = K / BK;
    load_stage(sb,          Wt, Xt, K, m0, brow, 0,  tid);
    CP_COMMIT();
    load_stage(sb + STAGE,  Wt, Xt, K, m0, brow, BK, tid);
    CP_COMMIT();

    for (int ch = 0; ch < nch; ++ch) {
        CP_WAIT(1);
        __syncthreads();

        if (ch + 2 < nch)
            load_stage(sb + (uint32_t)((ch + 2) % NSTAGE) * STAGE,
                       Wt, Xt, K, m0, brow, (ch + 2) * BK, tid);
        CP_COMMIT();

        const char* cur = smem + (size_t)(ch % NSTAGE) * STAGE;
        const char* sA  = cur;
        const char* sB  = cur + ATILE;

        #pragma unroll
        for (int ks = 0; ks < 4; ++ks) {
            uint32_t c0 = ((uint32_t)(2*ks)     ^ xm) << 4;
            uint32_t c1 = ((uint32_t)(2*ks + 1) ^ xm) << 4;

            uint32_t B0[4], B1[4];
            #pragma unroll
            for (int ni = 0; ni < 4; ++ni) {
                const char* bb = sB + bRow0 + ni*8*128;
                B0[ni] = *(const uint32_t*)(bb + c0);
                B1[ni] = *(const uint32_t*)(bb + c1);
            }
            #pragma unroll
            for (int mi = 0; mi < 4; ++mi) {
                const char* ab = sA + aRow0 + mi*16*128;
                uint32_t a0 = *(const uint32_t*)(ab + c0);
                uint32_t a1 = *(const uint32_t*)(ab + 1024 + c0);
                uint32_t a2 = *(const uint32_t*)(ab + c1);
                uint32_t a3 = *(const uint32_t*)(ab + 1024 + c1);
                #pragma unroll
                for (int ni = 0; ni < 4; ++ni)
                    mma_tf32(acc[mi][ni], a0, a1, a2, a3, B0[ni], B1[ni]);
            }
        }
    }
    __syncthreads();   // mainloop done before smem reuse

    // ---- stage fragments to smem as [t][m] (132-float padded rows) ----
    float* smemf = (float*)smem;
    #pragma unroll
    for (int mi = 0; mi < 4; ++mi) {
        int ma = wm*64 + mi*16 + (lane >> 2);
        #pragma unroll
        for (int ni = 0; ni < 4; ++ni) {
            int tc = wn*32 + ni*8 + (lane & 3)*2;
            float* st = smemf + tc*132;
            st[ma]        = acc[mi][ni][0];
            st[132 + ma]  = acc[mi][ni][1];
            st[ma + 8]    = acc[mi][ni][2];
            st[132 + ma + 8] = acc[mi][ni][3];
        }
    }
    __syncthreads();

    // ---- write phase: coalesced channel-major output -------------------------
    if (EPI == EPI_GLU) {
        int m = lane*4;
        int r0 = m0 + m;
        float b0a = bias[(r0&1)?(HH+(r0>>1)):(r0>>1)];
        float b0g = bias[((r0+1)&1)?(HH+((r0+1)>>1)):((r0+1)>>1)];
        float b1a = bias[((r0+2)&1)?(HH+((r0+2)>>1)):((r0+2)>>1)];
        float b1g = bias[((r0+3)&1)?(HH+((r0+3)>>1)):((r0+3)>>1)];
        #pragma unroll
        for (int p = 0; p < 16; ++p) {
            int r = p*8 + (tid >> 5);
            float4 z = *(float4*)(smemf + r*132 + m);
            float a0 = z.x + b0a, gg0 = z.y + b0g;
            float a1 = z.z + b1a, gg1 = z.w + b1g;
            float2 s;
            s.x = a0 / (1.0f + expf(-gg0));
            s.y = a1 / (1.0f + expf(-gg1));
            *(float2*)(OutF + ((size_t)b*TT + t0 + r)*HH + (m0>>1) + lane*2) = s;
        }
    } else if (EPI == EPI_TF) {
        int m = lane*4;
        float4 bi = *(const float4*)(bias + m0 + m);
        #pragma unroll
        for (int p = 0; p < 16; ++p) {
            int r = p*8 + (tid >> 5);
            float mv = mask[(size_t)b*TT + t0 + r];
            float4 v = *(float4*)(smemf + r*132 + m);
            uint4 o;
            o.x = tf32r(fmaxf(v.x + bi.x, 0.f) * mv);
            o.y = tf32r(fmaxf(v.y + bi.y, 0.f) * mv);
            o.z = tf32r(fmaxf(v.z + bi.z, 0.f) * mv);
            o.w = tf32r(fmaxf(v.w + bi.w, 0.f) * mv);
            *(uint4*)(OutT + ((size_t)b*TT + t0 + r)*ldo + m0 + m) = o;
        }
    } else {
        int m = lane*4;
        float4 bi = *(const float4*)(bias + m0 + m);
        #pragma unroll
        for (int p = 0; p < 16; ++p) {
            int r = p*8 + (tid >> 5);
            float mv = mask[(size_t)b*TT + t0 + r];
            float4 v = *(float4*)(smemf + r*132 + m);
            v.x = (v.x + bi.x) * mv;
            v.y = (v.y + bi.y) * mv;
            v.z = (v.z + bi.z) * mv;
            v.w = (v.w + bi.w) * mv;
            *(float4*)(OutF + ((size_t)b*TT + t0 + r)*HH + m0 + m) = v;
        }
    }
}

// ---------------- channel LayerNorm (channels contiguous), warp per token ---------
// MODE 0: v = res*mask + y; write x1 fp32 + tf32-rounded (x1*mask)
// MODE 1: v = res + y;      write fp32 only
template<int MODE>
__global__ __launch_bounds__(256)
void ln_kernel(const float* __restrict__ res, const float* __restrict__ yy,
               const float* __restrict__ mask,
               const float* __restrict__ gamma, const float* __restrict__ beta,
               float* __restrict__ outF, float* __restrict__ outT)
{
    int g = blockIdx.x*8 + (threadIdx.x >> 5);
    int lane = threadIdx.x & 31;
    size_t base = (size_t)g*HH;
    float mv = mask[g];

    float4 v[3];
    float s = 0.f, q = 0.f;
    #pragma unroll
    for (int j = 0; j < 3; ++j) {
        float4 r1 = *(const float4*)(res + base + lane*4 + j*128);
        float4 r2 = *(const float4*)(yy  + base + lane*4 + j*128);
        float4 t;
        if (MODE == 0) {
            t.x = fmaf(r1.x, mv, r2.x); t.y = fmaf(r1.y, mv, r2.y);
            t.z = fmaf(r1.z, mv, r2.z); t.w = fmaf(r1.w, mv, r2.w);
        } else {
            t.x = r1.x + r2.x; t.y = r1.y + r2.y;
            t.z = r1.z + r2.z; t.w = r1.w + r2.w;
        }
        v[j] = t;
        s += t.x + t.y + t.z + t.w;
        q += t.x*t.x + t.y*t.y + t.z*t.z + t.w*t.w;
    }
    #pragma unroll
    for (int off = 16; off; off >>= 1) {
        s += __shfl_xor_sync(0xffffffffu, s, off);
        q += __shfl_xor_sync(0xffffffffu, q, off);
    }
    float mu = s * (1.0f/HH);
    float rs = rsqrtf(q * (1.0f/HH) - mu*mu + 1e-4f);

    #pragma unroll
    for (int j = 0; j < 3; ++j) {
        float4 ga = *(const float4*)(gamma + lane*4 + j*128);
        float4 be = *(const float4*)(beta  + lane*4 + j*128);
        float4 t = v[j];
        t.x = (t.x - mu)*rs*ga.x + be.x;
        t.y = (t.y - mu)*rs*ga.y + be.y;
        t.z = (t.z - mu)*rs*ga.z + be.z;
        t.w = (t.w - mu)*rs*ga.w + be.w;
        *(float4*)(outF + base + lane*4 + j*128) = t;
        if (MODE == 0) {
            uint4 o;
            o.x = tf32r(t.x * mv);
            o.y = tf32r(t.y * mv);
            o.z = tf32r(t.z * mv);
            o.w = tf32r(t.w * mv);
            *(uint4*)(outT + base + lane*4 + j*128) = o;
        }
    }
}

// ---------------- host launch -----------------------------------------------------
extern "C" void kernel_launch(void* const* d_in, const int* in_sizes, int n_in,
                              void* d_out, int out_size)
{
    (void)in_sizes; (void)n_in; (void)out_size;
    const float* x      = (const float*)d_in[0];
    const float* mask   = (const float*)d_in[1];
    const float* log_dt = (const float*)d_in[2];
    const float* A_re   = (const float*)d_in[3];
    const float* A_im   = (const float*)d_in[4];
    const float* C_re   = (const float*)d_in[5];
    const float* C_im   = (const float*)d_in[6];
    const float* Dp     = (const float*)d_in[7];
    const float* Wout   = (const float*)d_in[8];
    const float* bout   = (const float*)d_in[9];
    const float* g1     = (const float*)d_in[10];
    const float* be1    = (const float*)d_in[11];
    const float* W1     = (const float*)d_in[12];
    const float* bf1    = (const float*)d_in[13];
    const float* W2     = (const float*)d_in[14];
    const float* bf2    = (const float*)d_in[15];
    const float* g2     = (const float*)d_in[16];
    const float* be2    = (const float*)d_in[17];

    float *ga, *gb, *gc, *xt, *ht, *woutt, *w1t, *w2t;
    cudaGetSymbolAddress((void**)&ga, g_a);
    cudaGetSymbolAddress((void**)&gb, g_b);
    cudaGetSymbolAddress((void**)&gc, g_c);
    cudaGetSymbolAddress((void**)&xt, g_xt);
    cudaGetSymbolAddress((void**)&ht, g_ht);
    cudaGetSymbolAddress((void**)&woutt, g_woutt);
    cudaGetSymbolAddress((void**)&w1t, g_w1t);
    cudaGetSymbolAddress((void**)&w2t, g_w2t);

    cudaFuncSetAttribute(gemm_mma<EPI_GLU >, cudaFuncAttributeMaxDynamicSharedMemorySize, GEMM_SMEM);
    cudaFuncSetAttribute(gemm_mma<EPI_TF  >, cudaFuncAttributeMaxDynamicSharedMemorySize, GEMM_SMEM);
    cudaFuncSetAttribute(gemm_mma<EPI_FP32>, cudaFuncAttributeMaxDynamicSharedMemorySize, GEMM_SMEM);

    // weight conversion (all layers, once)
    convw_perm <<<(LYR*2*HH*HH + 255)/256, 256>>>(Wout, woutt);
    convw_plain<<<(LYR*HF*HH   + 255)/256, 256>>>(W1, w1t, LYR*HF*HH);
    convw_plain<<<(LYR*HH*HF   + 255)/256, 256>>>(W2, w2t, LYR*HH*HF);

    // input to [B,T,H]
    transpose_in<<<dim3(TT/32, HH/32, BB), dim3(32, 8)>>>(x, ga);

    for (int l = 0; l < LYR; ++l) {
        // 1. scan -> tf32 operand [B,T,H]
        scan_kernel<<<(BB*HH)/4, 128>>>(ga, mask, log_dt, A_re, A_im, C_re, C_im, Dp,
                                        xt, l);
        // 2. Wout GEMM + fused GLU -> s4 fp32 (g_b)
        gemm_mma<EPI_GLU><<<dim3(TT/BN, (2*HH)/BM, BB), 256, GEMM_SMEM>>>(
            woutt + (size_t)l*2*HH*HH, xt, bout + (size_t)l*2*HH, mask,
            gb, nullptr, HH, 0);
        // 3. LN1 -> x1 fp32 (g_c) + tf32 operand
        ln_kernel<0><<<NTOK/8, 256>>>(ga, gb, mask, g1 + (size_t)l*HH, be1 + (size_t)l*HH,
                                      gc, xt);
        // 4. W1 GEMM + relu + mask -> tf32 hidden [B,T,HF]
        gemm_mma<EPI_TF><<<dim3(TT/BN, HF/BM, BB), 256, GEMM_SMEM>>>(
            w1t + (size_t)l*HF*HH, xt, bf1 + (size_t)l*HF, mask,
            nullptr, ht, HH, HF);
        // 5. W2 GEMM + mask -> o fp32 (g_b)
        gemm_mma<EPI_FP32><<<dim3(TT/BN, HH/BM, BB), 256, GEMM_SMEM>>>(
            w2t + (size_t)l*HH*HF, ht, bf2 + (size_t)l*HH, mask,
            gb, nullptr, HF, 0);
        // 6. LN2 -> next x fp32 (g_a)
        ln_kernel<1><<<NTOK/8, 256>>>(gc, gb, mask, g2 + (size_t)l*HH, be2 + (size_t)l*HH,
                                      ga, nullptr);
    }
    transpose_out<<<dim3(TT/32, HH/32, BB), dim3(32, 8)>>>(ga, mask, (float*)d_out);
}

// round 14
// speedup vs baseline: 3.7043x; 1.0767x over previous
#include <cuda_runtime.h>
#include <math.h>
#include <stdint.h>

#define LYR 6
#define BB  16
#define HH  384
#define TT  2048
#define N2  32
#define HF  1536
#define NTOK (BB*TT)

// ---------------- scratch (device globals) ----------------------------------------
__device__ float g_a[(size_t)NTOK*HH];   // xcur [B,T,H]
__device__ float g_b[(size_t)NTOK*HH];   // s4 / FFN out
__device__ float g_c[(size_t)NTOK*HH];   // x1 (LN1 out)
__device__ float g_xt[(size_t)NTOK*HH];  // tf32-rounded K=384 operand [B,T,H]
__device__ float g_ht[(size_t)NTOK*HF];  // tf32-rounded K=1536 operand [B,T,HF]
__device__ float g_woutt[LYR*2*HH*HH];   // GLU-permuted, fragment-packed tf32 weights
__device__ float g_w1t[LYR*HF*HH];
__device__ float g_w2t[LYR*HH*HF];

// ================= helpers =================
__device__ __forceinline__ uint32_t smem_u32(const void* p) {
    uint32_t a;
    asm("{ .reg .u64 t; cvta.to.shared.u64 t, %1; cvt.u32.u64 %0, t; }" : "=r"(a) : "l"(p));
    return a;
}
__device__ __forceinline__ void cpasync16(uint32_t saddr, const void* g) {
    asm volatile("cp.async.cg.shared.global [%0], [%1], 16;" :: "r"(saddr), "l"(g));
}
#define CP_COMMIT() asm volatile("cp.async.commit_group;" ::: "memory")
#define CP_WAIT(n)  asm volatile("cp.async.wait_group %0;" :: "n"(n) : "memory")

__device__ __forceinline__ uint32_t tf32r(float x) {
    uint32_t u;
    asm("cvt.rna.tf32.f32 %0, %1;" : "=r"(u) : "f"(x));
    return u;
}
__device__ __forceinline__ float tf32rf(float x) { return __uint_as_float(tf32r(x)); }

__device__ __forceinline__ void mma_tf32(float* d, uint32_t a0, uint32_t a1,
                                         uint32_t a2, uint32_t a3,
                                         uint32_t b0, uint32_t b1) {
    asm volatile("mma.sync.aligned.m16n8k8.row.col.f32.tf32.tf32.f32 "
        "{%0,%1,%2,%3}, {%4,%5,%6,%7}, {%8,%9}, {%0,%1,%2,%3};"
        : "+f"(d[0]), "+f"(d[1]), "+f"(d[2]), "+f"(d[3])
        : "r"(a0), "r"(a1), "r"(a2), "r"(a3), "r"(b0), "r"(b1));
}

// ---------------- weight conversion: tf32 + mma-fragment packing -------------------
// Packed layout per layer (M x K): tile (tm, tk) of 128x32 = 4096 floats; within,
// slot fs = mi*4 + ks in [0,32), lane in [0,32), j in [0,4):
//   packed[(((tm*(K/32) + tk)*32 + fs)*32 + lane)*4 + j]
//     = W[tm*128 + (fs>>2)*16 + (lane>>2) + (j&1)*8][tk*32 + (fs&3)*8 + (lane&3) + (j>>1)*4]
// so one LDS.128 yields {a0,a1,a2,a3} for mma.m16n8k8.
template<int GLU>
__global__ void convw_pack(const float* __restrict__ W, float* __restrict__ o,
                           int M, int K, int n)
{
    int i = blockIdx.x * blockDim.x + threadIdx.x;
    if (i >= n) return;
    int per = M * K;
    int l = i / per;
    int e = i % per;
    int j    = e & 3;
    int lane = (e >> 2) & 31;
    int fs   = (e >> 7) & 31;          // 32 slots per 128x32 tile
    int tile = e >> 12;                // 4096 floats per tile
    int ntK = K >> 5;
    int tk = tile % ntK, tm = tile / ntK;
    int mi = fs >> 2, ks = fs & 3;
    int r = tm*128 + mi*16 + (lane >> 2) + (j & 1)*8;
    int c = tk*32  + ks*8  + (lane & 3)  + (j >> 1)*4;
    int src_r = GLU ? ((r & 1) ? (M/2 + (r >> 1)) : (r >> 1)) : r;
    o[i] = tf32rf(W[(size_t)l*per + (size_t)src_r*K + c]);
}

// ---------------- transposes ------------------------------------------------------
__global__ void transpose_in(const float* __restrict__ in, float* __restrict__ out)
{
    __shared__ float tile[32][33];
    int b = blockIdx.z, t0 = blockIdx.x*32, h0 = blockIdx.y*32;
    int tx = threadIdx.x, ty = threadIdx.y;
    #pragma unroll
    for (int i = 0; i < 4; ++i)
        tile[ty + i*8][tx] = in[((size_t)b*HH + h0 + ty + i*8)*TT + t0 + tx];
    __syncthreads();
    #pragma unroll
    for (int i = 0; i < 4; ++i)
        out[((size_t)b*TT + t0 + ty + i*8)*HH + h0 + tx] = tile[tx][ty + i*8];
}
__global__ void transpose_out(const float* __restrict__ in, const float* __restrict__ mask,
                              float* __restrict__ out)
{
    __shared__ float tile[32][33];
    int b = blockIdx.z, t0 = blockIdx.x*32, h0 = blockIdx.y*32;
    int tx = threadIdx.x, ty = threadIdx.y;
    #pragma unroll
    for (int i = 0; i < 4; ++i)
        tile[ty + i*8][tx] = in[((size_t)b*TT + t0 + ty + i*8)*HH + h0 + tx];
    __syncthreads();
    float mv = mask[(size_t)b*TT + t0 + tx];
    #pragma unroll
    for (int i = 0; i < 4; ++i)
        out[((size_t)b*HH + h0 + ty + i*8)*TT + t0 + tx] = tile[tx][ty + i*8] * mv;
}

// ---------------- S4D scan: coalesced smem-staged I/O, 8 h per block --------------
__global__ __launch_bounds__(256)
void scan_kernel(const float* __restrict__ x, const float* __restrict__ mask,
                 const float* __restrict__ log_dt,
                 const float* __restrict__ A_re, const float* __restrict__ A_im,
                 const float* __restrict__ C_re, const float* __restrict__ C_im,
                 const float* __restrict__ Dp,
                 float* __restrict__ yt, int layer)
{
    __shared__ float sxT[32][9];        // [t][h'] masked input
    __shared__ float syo[32][9];        // [t][h'] output stage
    __shared__ float sc[8][32][33];
    int tid = threadIdx.x;
    int w = tid >> 5, lane = tid & 31;
    int gidx = blockIdx.x * 8;          // 8 consecutive h, same b (HH % 8 == 0)
    int b = gidx / HH, h0 = gidx % HH;
    int h = h0 + w;
    int lt = tid >> 3, lh = tid & 7;

    float dt = expf(log_dt[layer*HH + h]);
    int pidx = (layer*HH + h) * N2 + lane;
    float ar = A_re[pidx], ai = A_im[pidx];
    float dre = ar * dt, dim = ai * dt;
    float e   = expf(dre);
    float wre = e * cosf(dim);
    float wim = e * sinf(dim);
    float nre = wre - 1.0f, nim = wim;
    float d2  = ar*ar + ai*ai;
    float qre = (nre*ar + nim*ai) / d2;
    float qim = (nim*ar - nre*ai) / d2;
    float cre = C_re[pidx], cim = C_im[pidx];
    float cdre = cre*qre - cim*qim;
    float cdim = cre*qim + cim*qre;
    float Dv = Dp[layer*HH + h];

    float sre = 0.f, sim = 0.f;

    for (int c = 0; c < TT/32; ++c) {
        int t0 = c*32;
        float mval = mask[(size_t)b*TT + t0 + lt];
        sxT[lt][lh] = x[((size_t)b*TT + t0 + lt)*HH + h0 + lh] * mval;
        __syncthreads();

        #pragma unroll
        for (int j = 0; j < 32; ++j) {
            float xj = sxT[j][w];
            float tre = fmaf(wre, sre, fmaf(-wim, sim, xj));
            float tim = fmaf(wre, sim, wim * sre);
            sre = tre; sim = tim;
            sc[w][lane][j] = fmaf(cdre, sre, -cdim * sim);
        }
        __syncwarp();
        float sum = 0.f;
        #pragma unroll
        for (int n = 0; n < 32; ++n) sum += sc[w][n][lane];
        float yv = 2.0f*sum + Dv * sxT[lane][w];
        yv = 0.5f * yv * (1.0f + erff(yv * 0.70710678118654752f));
        syo[lane][w] = tf32rf(yv);
        __syncthreads();

        yt[((size_t)b*TT + t0 + lt)*HH + h0 + lh] = syo[lt][lh];
        __syncthreads();
    }
}

// ---------------- single-pass tf32 mma.sync GEMM ----------------------------------
// A: fragment-packed 16KB tiles (linear). B: 128B rows, 16B-chunk XOR swizzle.
#define BM 128
#define BN 128
#define BK 32
#define ATILE 16384
#define STAGE (2*ATILE)
#define NSTAGE 3
#define GEMM_SMEM (NSTAGE*STAGE)    // 98304; epilogue needs 128*132*4 = 67584

#define EPI_GLU  0
#define EPI_TF   1
#define EPI_FP32 2

__device__ __forceinline__ void load_stage(
    uint32_t sbase,
    const float* __restrict__ Wt, const float* __restrict__ Xt,
    int K, int m0, size_t brow, int k0, int tid)
{
    // A: contiguous packed tile
    const float* Wp = Wt + ((size_t)(m0 >> 7) * (K >> 5) + (k0 >> 5)) * 4096;
    #pragma unroll
    for (int i = 0; i < 4; ++i) {
        int s = tid + i*256;
        cpasync16(sbase + (uint32_t)s*16, Wp + s*4);
    }
    // B: row-major with XOR swizzle
    #pragma unroll
    for (int i = 0; i < 4; ++i) {
        int s = tid + i*256;
        int row = s >> 3, c = s & 7;
        uint32_t dst = sbase + ATILE + (uint32_t)row*128 + (uint32_t)((c ^ (row & 7)) << 4);
        cpasync16(dst, Xt + (brow + row)*K + k0 + c*4);
    }
}

template<int EPI>
__global__ __launch_bounds__(256, 2)
void gemm_mma(const float* __restrict__ Wt, const float* __restrict__ Xt,
              const float* __restrict__ bias, const float* __restrict__ mask,
              float* __restrict__ OutF, float* __restrict__ OutT,
              int K, int ldo)
{
    extern __shared__ char smem[];
    uint32_t sb = smem_u32(smem);
    int tid = threadIdx.x;
    int b  = blockIdx.z;
    int m0 = blockIdx.y * BM;
    int t0 = blockIdx.x * BN;
    size_t brow = (size_t)b*TT + t0;

    int w = tid >> 5, lane = tid & 31;
    int wm = w & 1, wn = w >> 1;

    float acc[4][4][4];
    #pragma unroll
    for (int i = 0; i < 4; ++i)
        #pragma unroll
        for (int j = 0; j < 4; ++j)
            #pragma unroll
            for (int q = 0; q < 4; ++q) acc[i][j][q] = 0.f;

    // B fragment addressing
    uint32_t xm  = (uint32_t)(lane >> 2);
    uint32_t bRow0 = (uint32_t)(wn*32 + (lane >> 2)) * 128 + (uint32_t)(lane & 3) * 4;
    // A packed per-warp base: slot = (wm*4+mi)*4 + ks, each slot 512B, lane*16 within
    uint32_t aLane = (uint32_t)lane * 16;

    int nch = K / BK;
    load_stage(sb,          Wt, Xt, K, m0, brow, 0,  tid);
    CP_COMMIT();
    load_stage(sb + STAGE,  Wt, Xt, K, m0, brow, BK, tid);
    CP_COMMIT();

    for (int ch = 0; ch < nch; ++ch) {
        CP_WAIT(1);
        __syncthreads();

        if (ch + 2 < nch)
            load_stage(sb + (uint32_t)((ch + 2) % NSTAGE) * STAGE,
                       Wt, Xt, K, m0, brow, (ch + 2) * BK, tid);
        CP_COMMIT();

        const char* cur = smem + (size_t)(ch % NSTAGE) * STAGE;
        const char* sA  = cur;
        const char* sB  = cur + ATILE;

        #pragma unroll
        for (int ks = 0; ks < 4; ++ks) {
            uint32_t c0 = ((uint32_t)(2*ks)     ^ xm) << 4;
            uint32_t c1 = ((uint32_t)(2*ks + 1) ^ xm) << 4;

            uint32_t B0[4], B1[4];
            #pragma unroll
            for (int ni = 0; ni < 4; ++ni) {
                const char* bb = sB + bRow0 + ni*8*128;
                B0[ni] = *(const uint32_t*)(bb + c0);
                B1[ni] = *(const uint32_t*)(bb + c1);
            }
            #pragma unroll
            for (int mi = 0; mi < 4; ++mi) {
                uint4 av = *(const uint4*)(sA + (uint32_t)(((wm*4 + mi)*4 + ks))*512 + aLane);
                #pragma unroll
                for (int ni = 0; ni < 4; ++ni)
                    mma_tf32(acc[mi][ni], av.x, av.y, av.z, av.w, B0[ni], B1[ni]);
            }
        }
    }
    __syncthreads();   // mainloop done before smem reuse

    // ---- stage fragments to smem as [t][m] (132-float padded rows) ----
    float* smemf = (float*)smem;
    #pragma unroll
    for (int mi = 0; mi < 4; ++mi) {
        int ma = wm*64 + mi*16 + (lane >> 2);
        #pragma unroll
        for (int ni = 0; ni < 4; ++ni) {
            int tc = wn*32 + ni*8 + (lane & 3)*2;
            float* st = smemf + tc*132;
            st[ma]        = acc[mi][ni][0];
            st[132 + ma]  = acc[mi][ni][1];
            st[ma + 8]    = acc[mi][ni][2];
            st[132 + ma + 8] = acc[mi][ni][3];
        }
    }
    __syncthreads();

    // ---- write phase: coalesced channel-major output -------------------------
    if (EPI == EPI_GLU) {
        int m = lane*4;
        int r0 = m0 + m;
        float b0a = bias[(r0&1)?(HH+(r0>>1)):(r0>>1)];
        float b0g = bias[((r0+1)&1)?(HH+((r0+1)>>1)):((r0+1)>>1)];
        float b1a = bias[((r0+2)&1)?(HH+((r0+2)>>1)):((r0+2)>>1)];
        float b1g = bias[((r0+3)&1)?(HH+((r0+3)>>1)):((r0+3)>>1)];
        #pragma unroll
        for (int p = 0; p < 16; ++p) {
            int r = p*8 + (tid >> 5);
            float4 z = *(float4*)(smemf + r*132 + m);
            float a0 = z.x + b0a, gg0 = z.y + b0g;
            float a1 = z.z + b1a, gg1 = z.w + b1g;
            float2 s;
            s.x = a0 / (1.0f + expf(-gg0));
            s.y = a1 / (1.0f + expf(-gg1));
            *(float2*)(OutF + ((size_t)b*TT + t0 + r)*HH + (m0>>1) + lane*2) = s;
        }
    } else if (EPI == EPI_TF) {
        int m = lane*4;
        float4 bi = *(const float4*)(bias + m0 + m);
        #pragma unroll
        for (int p = 0; p < 16; ++p) {
            int r = p*8 + (tid >> 5);
            float mv = mask[(size_t)b*TT + t0 + r];
            float4 v = *(float4*)(smemf + r*132 + m);
            uint4 o;
            o.x = tf32r(fmaxf(v.x + bi.x, 0.f) * mv);
            o.y = tf32r(fmaxf(v.y + bi.y, 0.f) * mv);
            o.z = tf32r(fmaxf(v.z + bi.z, 0.f) * mv);
            o.w = tf32r(fmaxf(v.w + bi.w, 0.f) * mv);
            *(uint4*)(OutT + ((size_t)b*TT + t0 + r)*ldo + m0 + m) = o;
        }
    } else {
        int m = lane*4;
        float4 bi = *(const float4*)(bias + m0 + m);
        #pragma unroll
        for (int p = 0; p < 16; ++p) {
            int r = p*8 + (tid >> 5);
            float mv = mask[(size_t)b*TT + t0 + r];
            float4 v = *(float4*)(smemf + r*132 + m);
            v.x = (v.x + bi.x) * mv;
            v.y = (v.y + bi.y) * mv;
            v.z = (v.z + bi.z) * mv;
            v.w = (v.w + bi.w) * mv;
            *(float4*)(OutF + ((size_t)b*TT + t0 + r)*HH + m0 + m) = v;
        }
    }
}

// ---------------- channel LayerNorm (channels contiguous), warp per token ---------
template<int MODE>
__global__ __launch_bounds__(256)
void ln_kernel(const float* __restrict__ res, const float* __restrict__ yy,
               const float* __restrict__ mask,
               const float* __restrict__ gamma, const float* __restrict__ beta,
               float* __restrict__ outF, float* __restrict__ outT)
{
    int g = blockIdx.x*8 + (threadIdx.x >> 5);
    int lane = threadIdx.x & 31;
    size_t base = (size_t)g*HH;
    float mv = mask[g];

    float4 v[3];
    float s = 0.f, q = 0.f;
    #pragma unroll
    for (int j = 0; j < 3; ++j) {
        float4 r1 = *(const float4*)(res + base + lane*4 + j*128);
        float4 r2 = *(const float4*)(yy  + base + lane*4 + j*128);
        float4 t;
        if (MODE == 0) {
            t.x = fmaf(r1.x, mv, r2.x); t.y = fmaf(r1.y, mv, r2.y);
            t.z = fmaf(r1.z, mv, r2.z); t.w = fmaf(r1.w, mv, r2.w);
        } else {
            t.x = r1.x + r2.x; t.y = r1.y + r2.y;
            t.z = r1.z + r2.z; t.w = r1.w + r2.w;
        }
        v[j] = t;
        s += t.x + t.y + t.z + t.w;
        q += t.x*t.x + t.y*t.y + t.z*t.z + t.w*t.w;
    }
    #pragma unroll
    for (int off = 16; off; off >>= 1) {
        s += __shfl_xor_sync(0xffffffffu, s, off);
        q += __shfl_xor_sync(0xffffffffu, q, off);
    }
    float mu = s * (1.0f/HH);
    float rs = rsqrtf(q * (1.0f/HH) - mu*mu + 1e-4f);

    #pragma unroll
    for (int j = 0; j < 3; ++j) {
        float4 ga = *(const float4*)(gamma + lane*4 + j*128);
        float4 be = *(const float4*)(beta  + lane*4 + j*128);
        float4 t = v[j];
        t.x = (t.x - mu)*rs*ga.x + be.x;
        t.y = (t.y - mu)*rs*ga.y + be.y;
        t.z = (t.z - mu)*rs*ga.z + be.z;
        t.w = (t.w - mu)*rs*ga.w + be.w;
        *(float4*)(outF + base + lane*4 + j*128) = t;
        if (MODE == 0) {
            uint4 o;
            o.x = tf32r(t.x * mv);
            o.y = tf32r(t.y * mv);
            o.z = tf32r(t.z * mv);
            o.w = tf32r(t.w * mv);
            *(uint4*)(outT + base + lane*4 + j*128) = o;
        }
    }
}

// ---------------- host launch -----------------------------------------------------
extern "C" void kernel_launch(void* const* d_in, const int* in_sizes, int n_in,
                              void* d_out, int out_size)
{
    (void)in_sizes; (void)n_in; (void)out_size;
    const float* x      = (const float*)d_in[0];
    const float* mask   = (const float*)d_in[1];
    const float* log_dt = (const float*)d_in[2];
    const float* A_re   = (const float*)d_in[3];
    const float* A_im   = (const float*)d_in[4];
    const float* C_re   = (const float*)d_in[5];
    const float* C_im   = (const float*)d_in[6];
    const float* Dp     = (const float*)d_in[7];
    const float* Wout   = (const float*)d_in[8];
    const float* bout   = (const float*)d_in[9];
    const float* g1     = (const float*)d_in[10];
    const float* be1    = (const float*)d_in[11];
    const float* W1     = (const float*)d_in[12];
    const float* bf1    = (const float*)d_in[13];
    const float* W2     = (const float*)d_in[14];
    const float* bf2    = (const float*)d_in[15];
    const float* g2     = (const float*)d_in[16];
    const float* be2    = (const float*)d_in[17];

    float *ga, *gb, *gc, *xt, *ht, *woutt, *w1t, *w2t;
    cudaGetSymbolAddress((void**)&ga, g_a);
    cudaGetSymbolAddress((void**)&gb, g_b);
    cudaGetSymbolAddress((void**)&gc, g_c);
    cudaGetSymbolAddress((void**)&xt, g_xt);
    cudaGetSymbolAddress((void**)&ht, g_ht);
    cudaGetSymbolAddress((void**)&woutt, g_woutt);
    cudaGetSymbolAddress((void**)&w1t, g_w1t);
    cudaGetSymbolAddress((void**)&w2t, g_w2t);

    cudaFuncSetAttribute(gemm_mma<EPI_GLU >, cudaFuncAttributeMaxDynamicSharedMemorySize, GEMM_SMEM);
    cudaFuncSetAttribute(gemm_mma<EPI_TF  >, cudaFuncAttributeMaxDynamicSharedMemorySize, GEMM_SMEM);
    cudaFuncSetAttribute(gemm_mma<EPI_FP32>, cudaFuncAttributeMaxDynamicSharedMemorySize, GEMM_SMEM);

    // weight conversion + fragment packing (all layers, once)
    convw_pack<1><<<(LYR*2*HH*HH + 255)/256, 256>>>(Wout, woutt, 2*HH, HH, LYR*2*HH*HH);
    convw_pack<0><<<(LYR*HF*HH   + 255)/256, 256>>>(W1,   w1t,   HF,   HH, LYR*HF*HH);
    convw_pack<0><<<(LYR*HH*HF   + 255)/256, 256>>>(W2,   w2t,   HH,   HF, LYR*HH*HF);

    // input to [B,T,H]
    transpose_in<<<dim3(TT/32, HH/32, BB), dim3(32, 8)>>>(x, ga);

    for (int l = 0; l < LYR; ++l) {
        scan_kernel<<<(BB*HH)/8, 256>>>(ga, mask, log_dt, A_re, A_im, C_re, C_im, Dp,
                                        xt, l);
        gemm_mma<EPI_GLU><<<dim3(TT/BN, (2*HH)/BM, BB), 256, GEMM_SMEM>>>(
            woutt + (size_t)l*2*HH*HH, xt, bout + (size_t)l*2*HH, mask,
            gb, nullptr, HH, 0);
        ln_kernel<0><<<NTOK/8, 256>>>(ga, gb, mask, g1 + (size_t)l*HH, be1 + (size_t)l*HH,
                                      gc, xt);
        gemm_mma<EPI_TF><<<dim3(TT/BN, HF/BM, BB), 256, GEMM_SMEM>>>(
            w1t + (size_t)l*HF*HH, xt, bf1 + (size_t)l*HF, mask,
            nullptr, ht, HH, HF);
        gemm_mma<EPI_FP32><<<dim3(TT/BN, HH/BM, BB), 256, GEMM_SMEM>>>(
            w2t + (size_t)l*HH*HF, ht, bf2 + (size_t)l*HH, mask,
            gb, nullptr, HF, 0);
        ln_kernel<1><<<NTOK/8, 256>>>(gc, gb, mask, g2 + (size_t)l*HH, be2 + (size_t)l*HH,
                                      ga, nullptr);
    }
    transpose_out<<<dim3(TT/32, HH/32, BB), dim3(32, 8)>>>(ga, mask, (float*)d_out);
}

// round 15
// speedup vs baseline: 5.4769x; 1.4785x over previous
#include <cuda_runtime.h>
#include <cuda_fp16.h>
#include <math.h>
#include <stdint.h>

#define LYR 6
#define BB  16
#define HH  384
#define TT  2048
#define N2  32
#define HF  1536
#define NTOK (BB*TT)

// ---------------- scratch (device globals) ----------------------------------------
__device__ float g_a[(size_t)NTOK*HH];   // xcur [B,T,H]
__device__ float g_b[(size_t)NTOK*HH];   // s4 / FFN out
__device__ float g_c[(size_t)NTOK*HH];   // x1 (LN1 out)
__device__ __half g_xt[(size_t)NTOK*HH];  // fp16 K=384 operand [B,T,H]
__device__ __half g_ht[(size_t)NTOK*HF];  // fp16 K=1536 operand [B,T,HF]
__device__ __half g_woutt[LYR*2*HH*HH];   // GLU-permuted, fragment-packed fp16 weights
__device__ __half g_w1t[LYR*HF*HH];
__device__ __half g_w2t[LYR*HH*HF];

// ================= helpers =================
__device__ __forceinline__ uint32_t smem_u32(const void* p) {
    uint32_t a;
    asm("{ .reg .u64 t; cvta.to.shared.u64 t, %1; cvt.u32.u64 %0, t; }" : "=r"(a) : "l"(p));
    return a;
}
__device__ __forceinline__ void cpasync16(uint32_t saddr, const void* g) {
    asm volatile("cp.async.cg.shared.global [%0], [%1], 16;" :: "r"(saddr), "l"(g));
}
#define CP_COMMIT() asm volatile("cp.async.commit_group;" ::: "memory")
#define CP_WAIT(n)  asm volatile("cp.async.wait_group %0;" :: "n"(n) : "memory")

__device__ __forceinline__ void ldmat2(uint32_t* r, uint32_t a) {
    asm volatile("ldmatrix.sync.aligned.m8n8.x2.shared.b16 {%0,%1}, [%2];"
        : "=r"(r[0]), "=r"(r[1]) : "r"(a));
}
__device__ __forceinline__ void mma_f16(float* d, uint32_t a0, uint32_t a1,
                                        uint32_t a2, uint32_t a3,
                                        uint32_t b0, uint32_t b1) {
    asm volatile("mma.sync.aligned.m16n8k16.row.col.f32.f16.f16.f32 "
        "{%0,%1,%2,%3}, {%4,%5,%6,%7}, {%8,%9}, {%0,%1,%2,%3};"
        : "+f"(d[0]), "+f"(d[1]), "+f"(d[2]), "+f"(d[3])
        : "r"(a0), "r"(a1), "r"(a2), "r"(a3), "r"(b0), "r"(b1));
}
__device__ __forceinline__ uint32_t h2u(__half2 v) {
    return *reinterpret_cast<uint32_t*>(&v);
}

// ---------------- weight conversion: fp16 + mma-fragment packing -------------------
// Packed per layer (M x K): tile (tm, tk) of 128x64 = 8192 halfs; within,
// slot fs = mi*4 + ks in [0,32), lane in [0,32), j in [0,8):
//   packed[(((tm*(K/64)+tk)*32 + fs)*32 + lane)*8 + j]
//     = W[tm*128 + (fs>>2)*16 + (lane>>2) + ((j>>1)&1)*8]
//        [tk*64 + (fs&3)*16 + (lane&3)*2 + (j&1) + ((j>>2)&1)*8]
// so one LDS.128 yields the full m16n8k16 A fragment {a0,a1,a2,a3}.
template<int GLU>
__global__ void convw_pack(const float* __restrict__ W, __half* __restrict__ o,
                           int M, int K, int n)
{
    int i = blockIdx.x * blockDim.x + threadIdx.x;
    if (i >= n) return;
    int per = M * K;
    int l = i / per;
    int e = i % per;
    int j    = e & 7;
    int lane = (e >> 3) & 31;
    int fs   = (e >> 8) & 31;          // 32 slots per 128x64 tile
    int tile = e >> 13;                // 8192 halfs per tile
    int ntK = K >> 6;
    int tk = tile % ntK, tm = tile / ntK;
    int mi = fs >> 2, ks = fs & 3;
    int r = tm*128 + mi*16 + (lane >> 2) + ((j >> 1) & 1)*8;
    int c = tk*64  + ks*16 + (lane & 3)*2 + (j & 1) + ((j >> 2) & 1)*8;
    int src_r = GLU ? ((r & 1) ? (M/2 + (r >> 1)) : (r >> 1)) : r;
    o[i] = __float2half(W[(size_t)l*per + (size_t)src_r*K + c]);
}

// ---------------- transposes ------------------------------------------------------
__global__ void transpose_in(const float* __restrict__ in, float* __restrict__ out)
{
    __shared__ float tile[32][33];
    int b = blockIdx.z, t0 = blockIdx.x*32, h0 = blockIdx.y*32;
    int tx = threadIdx.x, ty = threadIdx.y;
    #pragma unroll
    for (int i = 0; i < 4; ++i)
        tile[ty + i*8][tx] = in[((size_t)b*HH + h0 + ty + i*8)*TT + t0 + tx];
    __syncthreads();
    #pragma unroll
    for (int i = 0; i < 4; ++i)
        out[((size_t)b*TT + t0 + ty + i*8)*HH + h0 + tx] = tile[tx][ty + i*8];
}
__global__ void transpose_out(const float* __restrict__ in, const float* __restrict__ mask,
                              float* __restrict__ out)
{
    __shared__ float tile[32][33];
    int b = blockIdx.z, t0 = blockIdx.x*32, h0 = blockIdx.y*32;
    int tx = threadIdx.x, ty = threadIdx.y;
    #pragma unroll
    for (int i = 0; i < 4; ++i)
        tile[ty + i*8][tx] = in[((size_t)b*TT + t0 + ty + i*8)*HH + h0 + tx];
    __syncthreads();
    float mv = mask[(size_t)b*TT + t0 + tx];
    #pragma unroll
    for (int i = 0; i < 4; ++i)
        out[((size_t)b*HH + h0 + ty + i*8)*TT + t0 + tx] = tile[tx][ty + i*8] * mv;
}

// ---------------- S4D scan: coalesced smem-staged I/O, 8 h per block --------------
__global__ __launch_bounds__(256)
void scan_kernel(const float* __restrict__ x, const float* __restrict__ mask,
                 const float* __restrict__ log_dt,
                 const float* __restrict__ A_re, const float* __restrict__ A_im,
                 const float* __restrict__ C_re, const float* __restrict__ C_im,
                 const float* __restrict__ Dp,
                 __half* __restrict__ yt, int layer)
{
    __shared__ float sxT[32][9];        // [t][h'] masked input
    __shared__ float syo[32][9];        // [t][h'] output stage
    __shared__ float sc[8][32][33];
    int tid = threadIdx.x;
    int w = tid >> 5, lane = tid & 31;
    int gidx = blockIdx.x * 8;          // 8 consecutive h, same b (HH % 8 == 0)
    int b = gidx / HH, h0 = gidx % HH;
    int h = h0 + w;
    int lt = tid >> 3, lh = tid & 7;

    float dt = expf(log_dt[layer*HH + h]);
    int pidx = (layer*HH + h) * N2 + lane;
    float ar = A_re[pidx], ai = A_im[pidx];
    float dre = ar * dt, dim = ai * dt;
    float e   = expf(dre);
    float wre = e * cosf(dim);
    float wim = e * sinf(dim);
    float nre = wre - 1.0f, nim = wim;
    float d2  = ar*ar + ai*ai;
    float qre = (nre*ar + nim*ai) / d2;
    float qim = (nim*ar - nre*ai) / d2;
    float cre = C_re[pidx], cim = C_im[pidx];
    float cdre = cre*qre - cim*qim;
    float cdim = cre*qim + cim*qre;
    float Dv = Dp[layer*HH + h];

    float sre = 0.f, sim = 0.f;

    for (int c = 0; c < TT/32; ++c) {
        int t0 = c*32;
        float mval = mask[(size_t)b*TT + t0 + lt];
        sxT[lt][lh] = x[((size_t)b*TT + t0 + lt)*HH + h0 + lh] * mval;
        __syncthreads();

        #pragma unroll
        for (int j = 0; j < 32; ++j) {
            float xj = sxT[j][w];
            float tre = fmaf(wre, sre, fmaf(-wim, sim, xj));
            float tim = fmaf(wre, sim, wim * sre);
            sre = tre; sim = tim;
            sc[w][lane][j] = fmaf(cdre, sre, -cdim * sim);
        }
        __syncwarp();
        float sum = 0.f;
        #pragma unroll
        for (int n = 0; n < 32; ++n) sum += sc[w][n][lane];
        float yv = 2.0f*sum + Dv * sxT[lane][w];
        yv = 0.5f * yv * (1.0f + erff(yv * 0.70710678118654752f));
        syo[lane][w] = yv;
        __syncthreads();

        yt[((size_t)b*TT + t0 + lt)*HH + h0 + lh] = __float2half(syo[lt][lh]);
        __syncthreads();
    }
}

// ---------------- single-pass fp16 mma.sync GEMM (BK=64) --------------------------
// A: fragment-packed 16KB tiles (linear). B: 128B rows (=64 fp16), XOR swizzle.
#define BM 128
#define BN 128
#define BK 64
#define ATILE 16384                 // 128x64 fp16 packed
#define STAGE (2*ATILE)             // A + B = 32KB
#define NSTAGE 3
#define GEMM_SMEM (NSTAGE*STAGE)    // 98304; epilogue needs 128*132*4 = 67584

#define EPI_GLU  0
#define EPI_F16  1
#define EPI_FP32 2

__device__ __forceinline__ void load_stage(
    uint32_t sbase,
    const __half* __restrict__ Wt, const __half* __restrict__ Xt,
    int K, int m0, size_t brow, int k0, int tid)
{
    // A: contiguous packed tile (8192 halfs)
    const __half* Wp = Wt + ((size_t)(m0 >> 7) * (K >> 6) + (k0 >> 6)) * 8192;
    #pragma unroll
    for (int i = 0; i < 4; ++i) {
        int s = tid + i*256;
        cpasync16(sbase + (uint32_t)s*16, Wp + s*8);
    }
    // B: 128 t-rows x 64 fp16 (128B rows), 16B-chunk XOR swizzle
    #pragma unroll
    for (int i = 0; i < 4; ++i) {
        int s = tid + i*256;
        int row = s >> 3, c = s & 7;
        uint32_t dst = sbase + ATILE + (uint32_t)row*128 + (uint32_t)((c ^ (row & 7)) << 4);
        cpasync16(dst, Xt + (brow + row)*K + k0 + c*8);
    }
}

template<int EPI>
__global__ __launch_bounds__(256, 2)
void gemm_mma(const __half* __restrict__ Wt, const __half* __restrict__ Xt,
              const float* __restrict__ bias, const float* __restrict__ mask,
              float* __restrict__ OutF, __half* __restrict__ OutH,
              int K, int ldo)
{
    extern __shared__ char smem[];
    uint32_t sb = smem_u32(smem);
    int tid = threadIdx.x;
    int b  = blockIdx.z;
    int m0 = blockIdx.y * BM;
    int t0 = blockIdx.x * BN;
    size_t brow = (size_t)b*TT + t0;

    int w = tid >> 5, lane = tid & 31;
    int wm = w & 1, wn = w >> 1;

    float acc[4][4][4];
    #pragma unroll
    for (int i = 0; i < 4; ++i)
        #pragma unroll
        for (int j = 0; j < 4; ++j)
            #pragma unroll
            for (int q = 0; q < 4; ++q) acc[i][j][q] = 0.f;

    // B ldmatrix addressing: row = wn*32 + ni*8 + (lane&7); k-half by lane>>3.
    uint32_t rB7   = (uint32_t)(lane & 7);
    uint32_t half_ = (uint32_t)((lane >> 3) & 1);
    uint32_t bRow0 = (uint32_t)(wn*32 + (lane & 7)) * 128;
    // A packed: slot = (wm*4+mi)*4 + ks, 512B/slot, lane*16 within
    uint32_t aLane = (uint32_t)lane * 16;

    int nch = K / BK;
    load_stage(sb,          Wt, Xt, K, m0, brow, 0,  tid);
    CP_COMMIT();
    load_stage(sb + STAGE,  Wt, Xt, K, m0, brow, BK, tid);
    CP_COMMIT();

    for (int ch = 0; ch < nch; ++ch) {
        CP_WAIT(1);
        __syncthreads();

        if (ch + 2 < nch)
            load_stage(sb + (uint32_t)((ch + 2) % NSTAGE) * STAGE,
                       Wt, Xt, K, m0, brow, (ch + 2) * BK, tid);
        CP_COMMIT();

        uint32_t cur = sb + (uint32_t)(ch % NSTAGE) * STAGE;
        const char* sA = smem + (cur - sb);
        uint32_t sB = cur + ATILE;

        #pragma unroll
        for (int ks = 0; ks < 4; ++ks) {
            uint32_t cx = (uint32_t)((((uint32_t)(ks*2) + half_) ^ rB7) << 4);

            uint32_t B01[4][2];
            #pragma unroll
            for (int ni = 0; ni < 4; ++ni)
                ldmat2(B01[ni], sB + bRow0 + (uint32_t)ni*1024 + cx);

            #pragma unroll
            for (int mi = 0; mi < 4; ++mi) {
                uint4 av = *(const uint4*)(sA + (uint32_t)(((wm*4 + mi)*4 + ks))*512 + aLane);
                #pragma unroll
                for (int ni = 0; ni < 4; ++ni)
                    mma_f16(acc[mi][ni], av.x, av.y, av.z, av.w, B01[ni][0], B01[ni][1]);
            }
        }
    }
    __syncthreads();   // mainloop done before smem reuse

    // ---- stage fragments to smem as [t][m] (132-float padded rows) ----
    float* smemf = (float*)smem;
    #pragma unroll
    for (int mi = 0; mi < 4; ++mi) {
        int ma = wm*64 + mi*16 + (lane >> 2);
        #pragma unroll
        for (int ni = 0; ni < 4; ++ni) {
            int tc = wn*32 + ni*8 + (lane & 3)*2;
            float* st = smemf + tc*132;
            st[ma]        = acc[mi][ni][0];
            st[132 + ma]  = acc[mi][ni][1];
            st[ma + 8]    = acc[mi][ni][2];
            st[132 + ma + 8] = acc[mi][ni][3];
        }
    }
    __syncthreads();

    // ---- write phase: coalesced channel-major output -------------------------
    if (EPI == EPI_GLU) {
        int m = lane*4;
        int r0 = m0 + m;
        float b0a = bias[(r0&1)?(HH+(r0>>1)):(r0>>1)];
        float b0g = bias[((r0+1)&1)?(HH+((r0+1)>>1)):((r0+1)>>1)];
        float b1a = bias[((r0+2)&1)?(HH+((r0+2)>>1)):((r0+2)>>1)];
        float b1g = bias[((r0+3)&1)?(HH+((r0+3)>>1)):((r0+3)>>1)];
        #pragma unroll
        for (int p = 0; p < 16; ++p) {
            int r = p*8 + (tid >> 5);
            float4 z = *(float4*)(smemf + r*132 + m);
            float a0 = z.x + b0a, gg0 = z.y + b0g;
            float a1 = z.z + b1a, gg1 = z.w + b1g;
            float2 s;
            s.x = a0 / (1.0f + expf(-gg0));
            s.y = a1 / (1.0f + expf(-gg1));
            *(float2*)(OutF + ((size_t)b*TT + t0 + r)*HH + (m0>>1) + lane*2) = s;
        }
    } else if (EPI == EPI_F16) {
        int m = lane*4;
        float4 bi = *(const float4*)(bias + m0 + m);
        #pragma unroll
        for (int p = 0; p < 16; ++p) {
            int r = p*8 + (tid >> 5);
            float mv = mask[(size_t)b*TT + t0 + r];
            float4 v = *(float4*)(smemf + r*132 + m);
            v.x = fmaxf(v.x + bi.x, 0.f) * mv;
            v.y = fmaxf(v.y + bi.y, 0.f) * mv;
            v.z = fmaxf(v.z + bi.z, 0.f) * mv;
            v.w = fmaxf(v.w + bi.w, 0.f) * mv;
            uint2 o;
            o.x = h2u(__floats2half2_rn(v.x, v.y));
            o.y = h2u(__floats2half2_rn(v.z, v.w));
            *(uint2*)(OutH + ((size_t)b*TT + t0 + r)*ldo + m0 + m) = o;
        }
    } else {
        int m = lane*4;
        float4 bi = *(const float4*)(bias + m0 + m);
        #pragma unroll
        for (int p = 0; p < 16; ++p) {
            int r = p*8 + (tid >> 5);
            float mv = mask[(size_t)b*TT + t0 + r];
            float4 v = *(float4*)(smemf + r*132 + m);
            v.x = (v.x + bi.x) * mv;
            v.y = (v.y + bi.y) * mv;
            v.z = (v.z + bi.z) * mv;
            v.w = (v.w + bi.w) * mv;
            *(float4*)(OutF + ((size_t)b*TT + t0 + r)*HH + m0 + m) = v;
        }
    }
}

// ---------------- channel LayerNorm (channels contiguous), warp per token ---------
// MODE 0: v = res*mask + y; write x1 fp32 + fp16 (x1*mask)
// MODE 1: v = res + y;      write fp32 only
template<int MODE>
__global__ __launch_bounds__(256)
void ln_kernel(const float* __restrict__ res, const float* __restrict__ yy,
               const float* __restrict__ mask,
               const float* __restrict__ gamma, const float* __restrict__ beta,
               float* __restrict__ outF, __half* __restrict__ outH)
{
    int g = blockIdx.x*8 + (threadIdx.x >> 5);
    int lane = threadIdx.x & 31;
    size_t base = (size_t)g*HH;
    float mv = mask[g];

    float4 v[3];
    float s = 0.f, q = 0.f;
    #pragma unroll
    for (int j = 0; j < 3; ++j) {
        float4 r1 = *(const float4*)(res + base + lane*4 + j*128);
        float4 r2 = *(const float4*)(yy  + base + lane*4 + j*128);
        float4 t;
        if (MODE == 0) {
            t.x = fmaf(r1.x, mv, r2.x); t.y = fmaf(r1.y, mv, r2.y);
            t.z = fmaf(r1.z, mv, r2.z); t.w = fmaf(r1.w, mv, r2.w);
        } else {
            t.x = r1.x + r2.x; t.y = r1.y + r2.y;
            t.z = r1.z + r2.z; t.w = r1.w + r2.w;
        }
        v[j] = t;
        s += t.x + t.y + t.z + t.w;
        q += t.x*t.x + t.y*t.y + t.z*t.z + t.w*t.w;
    }
    #pragma unroll
    for (int off = 16; off; off >>= 1) {
        s += __shfl_xor_sync(0xffffffffu, s, off);
        q += __shfl_xor_sync(0xffffffffu, q, off);
    }
    float mu = s * (1.0f/HH);
    float rs = rsqrtf(q * (1.0f/HH) - mu*mu + 1e-4f);

    #pragma unroll
    for (int j = 0; j < 3; ++j) {
        float4 ga = *(const float4*)(gamma + lane*4 + j*128);
        float4 be = *(const float4*)(beta  + lane*4 + j*128);
        float4 t = v[j];
        t.x = (t.x - mu)*rs*ga.x + be.x;
        t.y = (t.y - mu)*rs*ga.y + be.y;
        t.z = (t.z - mu)*rs*ga.z + be.z;
        t.w = (t.w - mu)*rs*ga.w + be.w;
        *(float4*)(outF + base + lane*4 + j*128) = t;
        if (MODE == 0) {
            uint2 o;
            o.x = h2u(__floats2half2_rn(t.x * mv, t.y * mv));
            o.y = h2u(__floats2half2_rn(t.z * mv, t.w * mv));
            *(uint2*)(outH + base + lane*4 + j*128) = o;
        }
    }
}

// ---------------- host launch -----------------------------------------------------
extern "C" void kernel_launch(void* const* d_in, const int* in_sizes, int n_in,
                              void* d_out, int out_size)
{
    (void)in_sizes; (void)n_in; (void)out_size;
    const float* x      = (const float*)d_in[0];
    const float* mask   = (const float*)d_in[1];
    const float* log_dt = (const float*)d_in[2];
    const float* A_re   = (const float*)d_in[3];
    const float* A_im   = (const float*)d_in[4];
    const float* C_re   = (const float*)d_in[5];
    const float* C_im   = (const float*)d_in[6];
    const float* Dp     = (const float*)d_in[7];
    const float* Wout   = (const float*)d_in[8];
    const float* bout   = (const float*)d_in[9];
    const float* g1     = (const float*)d_in[10];
    const float* be1    = (const float*)d_in[11];
    const float* W1     = (const float*)d_in[12];
    const float* bf1    = (const float*)d_in[13];
    const float* W2     = (const float*)d_in[14];
    const float* bf2    = (const float*)d_in[15];
    const float* g2     = (const float*)d_in[16];
    const float* be2    = (const float*)d_in[17];

    float *ga, *gb, *gc;
    __half *xt, *ht, *woutt, *w1t, *w2t;
    cudaGetSymbolAddress((void**)&ga, g_a);
    cudaGetSymbolAddress((void**)&gb, g_b);
    cudaGetSymbolAddress((void**)&gc, g_c);
    cudaGetSymbolAddress((void**)&xt, g_xt);
    cudaGetSymbolAddress((void**)&ht, g_ht);
    cudaGetSymbolAddress((void**)&woutt, g_woutt);
    cudaGetSymbolAddress((void**)&w1t, g_w1t);
    cudaGetSymbolAddress((void**)&w2t, g_w2t);

    cudaFuncSetAttribute(gemm_mma<EPI_GLU >, cudaFuncAttributeMaxDynamicSharedMemorySize, GEMM_SMEM);
    cudaFuncSetAttribute(gemm_mma<EPI_F16 >, cudaFuncAttributeMaxDynamicSharedMemorySize, GEMM_SMEM);
    cudaFuncSetAttribute(gemm_mma<EPI_FP32>, cudaFuncAttributeMaxDynamicSharedMemorySize, GEMM_SMEM);

    // weight conversion + fragment packing (all layers, once)
    convw_pack<1><<<(LYR*2*HH*HH + 255)/256, 256>>>(Wout, woutt, 2*HH, HH, LYR*2*HH*HH);
    convw_pack<0><<<(LYR*HF*HH   + 255)/256, 256>>>(W1,   w1t,   HF,   HH, LYR*HF*HH);
    convw_pack<0><<<(LYR*HH*HF   + 255)/256, 256>>>(W2,   w2t,   HH,   HF, LYR*HH*HF);

    // input to [B,T,H]
    transpose_in<<<dim3(TT/32, HH/32, BB), dim3(32, 8)>>>(x, ga);

    for (int l = 0; l < LYR; ++l) {
        scan_kernel<<<(BB*HH)/8, 256>>>(ga, mask, log_dt, A_re, A_im, C_re, C_im, Dp,
                                        xt, l);
        gemm_mma<EPI_GLU><<<dim3(TT/BN, (2*HH)/BM, BB), 256, GEMM_SMEM>>>(
            woutt + (size_t)l*2*HH*HH, xt, bout + (size_t)l*2*HH, mask,
            gb, nullptr, HH, 0);
        ln_kernel<0><<<NTOK/8, 256>>>(ga, gb, mask, g1 + (size_t)l*HH, be1 + (size_t)l*HH,
                                      gc, xt);
        gemm_mma<EPI_F16><<<dim3(TT/BN, HF/BM, BB), 256, GEMM_SMEM>>>(
            w1t + (size_t)l*HF*HH, xt, bf1 + (size_t)l*HF, mask,
            nullptr, ht, HH, HF);
        gemm_mma<EPI_FP32><<<dim3(TT/BN, HH/BM, BB), 256, GEMM_SMEM>>>(
            w2t + (size_t)l*HH*HF, ht, bf2 + (size_t)l*HH, mask,
            gb, nullptr, HF, 0);
        ln_kernel<1><<<NTOK/8, 256>>>(gc, gb, mask, g2 + (size_t)l*HH, be2 + (size_t)l*HH,
                                      ga, nullptr);
    }
    transpose_out<<<dim3(TT/32, HH/32, BB), dim3(32, 8)>>>(ga, mask, (float*)d_out);
}